// round 14
// baseline (speedup 1.0000x reference)
#include <cuda_runtime.h>
#include <cuda_bf16.h>
#include <cuda_fp16.h>
#include <cstdint>

#define NODES 100000
#define EDGES 3200000
#define FEAT  128

// ---------------- scratch (static device memory; no allocation) ----------------
__device__ __half g_agg16[(size_t)NODES * FEAT];
__device__ float  g_h32A [(size_t)NODES * FEAT];
__device__ float  g_h32B [(size_t)NODES * FEAT];
__device__ __half g_x16  [(size_t)NODES * FEAT];
__device__ __half g_h16A [(size_t)NODES * FEAT];
__device__ __half g_h16B [(size_t)NODES * FEAT];
__device__ float  g_invd[NODES];
__device__ int    g_degi[NODES];
__device__ int    g_off [NODES + 1];
__device__ int    g_pos [NODES];
__device__ int    g_bsum[128];
__device__ int    g_csr [EDGES];
__device__ float  g_y   [(size_t)NODES * 16];              // cols 0-7: l-proj, 8-15: r-proj(+bias)
__device__ __nv_bfloat16 g_whi[6 * 16384];
__device__ __nv_bfloat16 g_wlo[6 * 16384];

// ================= helpers =================
__device__ __forceinline__ uint32_t smem_u32(const void* p) {
    uint32_t a;
    asm("{ .reg .u64 t; cvta.to.shared.u64 t, %1; cvt.u32.u64 %0, t; }" : "=r"(a) : "l"(p));
    return a;
}

__device__ __forceinline__ uint32_t pack_bf16x2(float a, float b) {
    __nv_bfloat162 h = __floats2bfloat162_rn(a, b);
    return reinterpret_cast<uint32_t&>(h);
}

__device__ __forceinline__ void ldsm_x4(uint32_t (&r)[4], uint32_t addr) {
    asm volatile("ldmatrix.sync.aligned.m8n8.x4.shared.b16 {%0,%1,%2,%3}, [%4];"
                 : "=r"(r[0]), "=r"(r[1]), "=r"(r[2]), "=r"(r[3]) : "r"(addr));
}

__device__ __forceinline__ void mma_bf16(float (&d)[4], const uint32_t (&a)[4],
                                         uint32_t b0, uint32_t b1) {
    asm volatile("mma.sync.aligned.m16n8k16.row.col.f32.bf16.bf16.f32 "
                 "{%0,%1,%2,%3}, {%4,%5,%6,%7}, {%8,%9}, {%0,%1,%2,%3};"
                 : "+f"(d[0]), "+f"(d[1]), "+f"(d[2]), "+f"(d[3])
                 : "r"(a[0]), "r"(a[1]), "r"(a[2]), "r"(a[3]), "r"(b0), "r"(b1));
}

__device__ __forceinline__ void acc_u4(float (&acc)[8], uint4 u) {
    float2 f0 = __half22float2(reinterpret_cast<__half2&>(u.x));
    float2 f1 = __half22float2(reinterpret_cast<__half2&>(u.y));
    float2 f2 = __half22float2(reinterpret_cast<__half2&>(u.z));
    float2 f3 = __half22float2(reinterpret_cast<__half2&>(u.w));
    acc[0] += f0.x; acc[1] += f0.y; acc[2] += f1.x; acc[3] += f1.y;
    acc[4] += f2.x; acc[5] += f2.y; acc[6] += f3.x; acc[7] += f3.y;
}

__device__ __forceinline__ float4 load_h4_as_f4(const __half* p) {
    uint2 u = *reinterpret_cast<const uint2*>(p);
    float2 a = __half22float2(reinterpret_cast<__half2&>(u.x));
    float2 b = __half22float2(reinterpret_cast<__half2&>(u.y));
    return make_float4(a.x, a.y, b.x, b.y);
}

__device__ __forceinline__ void split_store(char* smem, uint32_t offHi, uint32_t offLo, float4 v) {
    float hx = __bfloat162float(__float2bfloat16_rn(v.x));
    float hy = __bfloat162float(__float2bfloat16_rn(v.y));
    float hz = __bfloat162float(__float2bfloat16_rn(v.z));
    float hw = __bfloat162float(__float2bfloat16_rn(v.w));
    uint2 hi2 = make_uint2(pack_bf16x2(v.x, v.y), pack_bf16x2(v.z, v.w));
    uint2 lo2 = make_uint2(pack_bf16x2(v.x - hx, v.y - hy), pack_bf16x2(v.z - hz, v.w - hw));
    *reinterpret_cast<uint2*>(smem + offHi) = hi2;
    *reinterpret_cast<uint2*>(smem + offLo) = lo2;
}

// ---------------- merged prep: cvt16 | wsplit | hist(4 edges/thread), role by block range ----------------
__global__ __launch_bounds__(256) void prep_kernel(
        const float* __restrict__ x, __half* __restrict__ x16, int n4, int cvtBlocks,
        const float* __restrict__ w0, const float* __restrict__ w1,
        const float* __restrict__ w2, const float* __restrict__ w3,
        const float* __restrict__ w4, const float* __restrict__ w5,
        __nv_bfloat16* __restrict__ whi, __nv_bfloat16* __restrict__ wlo, int wsBlocks,
        const int* __restrict__ dst, int* __restrict__ degi, int E4) {
    int blk = blockIdx.x;
    int tid = threadIdx.x;

    if (blk < cvtBlocks) {
        int i = blk * 256 + tid;
        if (i < n4) {
            float4 v = reinterpret_cast<const float4*>(x)[i];
            __half2 h0 = __floats2half2_rn(v.x, v.y);
            __half2 h1 = __floats2half2_rn(v.z, v.w);
            uint2 o = make_uint2(reinterpret_cast<uint32_t&>(h0), reinterpret_cast<uint32_t&>(h1));
            reinterpret_cast<uint2*>(x16)[i] = o;
        }
        return;
    }
    blk -= cvtBlocks;

    if (blk < wsBlocks) {
        int i = blk * 256 + tid;
        if (i < 6 * 4096) {
            const float* src;
            switch (i >> 12) {
                case 0: src = w0; break; case 1: src = w1; break; case 2: src = w2; break;
                case 3: src = w3; break; case 4: src = w4; break; default: src = w5; break;
            }
            float4 v = reinterpret_cast<const float4*>(src)[i & 4095];
            float hx = __bfloat162float(__float2bfloat16_rn(v.x));
            float hy = __bfloat162float(__float2bfloat16_rn(v.y));
            float hz = __bfloat162float(__float2bfloat16_rn(v.z));
            float hw = __bfloat162float(__float2bfloat16_rn(v.w));
            uint2 hi2 = make_uint2(pack_bf16x2(v.x, v.y), pack_bf16x2(v.z, v.w));
            uint2 lo2 = make_uint2(pack_bf16x2(v.x - hx, v.y - hy), pack_bf16x2(v.z - hz, v.w - hw));
            reinterpret_cast<uint2*>(whi)[i] = hi2;
            reinterpret_cast<uint2*>(wlo)[i] = lo2;
        }
        return;
    }
    blk -= wsBlocks;

    // degree histogram: 4 edges per thread (int4)
    int e = blk * 256 + tid;
    if (e < E4) {
        int4 d = reinterpret_cast<const int4*>(dst)[e];
        atomicAdd(&degi[d.x], 1);
        atomicAdd(&degi[d.y], 1);
        atomicAdd(&degi[d.z], 1);
        atomicAdd(&degi[d.w], 1);
    }
}

// ---------------- CSR scans ----------------
__global__ void scan1_kernel(const int* __restrict__ degi, int* __restrict__ off,
                             int* __restrict__ bsum, int n) {
    __shared__ int s[1024];
    int t = threadIdx.x;
    int i = blockIdx.x * 1024 + t;
    int v = (i < n) ? degi[i] : 0;
    s[t] = v;
    __syncthreads();
#pragma unroll
    for (int d = 1; d < 1024; d <<= 1) {
        int x = (t >= d) ? s[t - d] : 0;
        __syncthreads();
        s[t] += x;
        __syncthreads();
    }
    if (i < n) off[i] = s[t] - v;
    if (t == 1023) bsum[blockIdx.x] = s[t];
}

// scan3 with inline bsum scan (scan2 merged)
__global__ void scan3_kernel(int* __restrict__ off, const int* __restrict__ bsum,
                             int* __restrict__ pos, const int* __restrict__ degi,
                             float* __restrict__ invd, int n, int E, int nb) {
    __shared__ int s[128];
    int t = threadIdx.x;
    int v = 0;
    if (t < 128) {
        v = (t < nb) ? bsum[t] : 0;
        s[t] = v;
    }
    __syncthreads();
#pragma unroll
    for (int d = 1; d < 128; d <<= 1) {
        int x = 0;
        if (t < 128 && t >= d) x = s[t - d];
        __syncthreads();
        if (t < 128) s[t] += x;
        __syncthreads();
    }
    if (t < 128) s[t] -= v;   // exclusive
    __syncthreads();

    int i = blockIdx.x * blockDim.x + t;
    if (i < n) {
        int o = off[i] + s[i >> 10];
        off[i] = o;
        pos[i] = o;
        invd[i] = 1.0f / fmaxf((float)degi[i], 1.0f);
    }
    if (i == 0) off[n] = E;
}

// vectorized fill: 4 edges per thread (4 independent atomics in flight)
__global__ void fill_kernel(const int* __restrict__ src, const int* __restrict__ dst,
                            int* __restrict__ pos, int* __restrict__ csr, int E4) {
    int e = blockIdx.x * blockDim.x + threadIdx.x;   // quad index
    if (e < E4) {
        int4 s = reinterpret_cast<const int4*>(src)[e];
        int4 d = reinterpret_cast<const int4*>(dst)[e];
        int p0 = atomicAdd(&pos[d.x], 1);
        int p1 = atomicAdd(&pos[d.y], 1);
        int p2 = atomicAdd(&pos[d.z], 1);
        int p3 = atomicAdd(&pos[d.w], 1);
        csr[p0] = s.x;
        csr[p1] = s.y;
        csr[p2] = s.z;
        csr[p3] = s.w;
    }
}

// ---------------- gather-mean: half-warp per node, fp16 in -> fp16 agg out, unroll 8 ----------------
__global__ __launch_bounds__(256) void gather16_kernel(
        const __half* __restrict__ feat, __half* __restrict__ agg16,
        const int* __restrict__ csr, const int* __restrict__ off,
        const float* __restrict__ invd, int n) {
    int gtid = blockIdx.x * blockDim.x + threadIdx.x;
    int node = gtid >> 4;
    int lane = gtid & 15;
    if (node >= n) return;

    int beg = off[node];
    int end = off[node + 1];

    float acc[8];
#pragma unroll
    for (int k = 0; k < 8; k++) acc[k] = 0.0f;

    const __half* fp = feat + lane * 8;

    int j = beg;
    for (; j + 7 < end; j += 8) {
        int idx[8];
#pragma unroll
        for (int u = 0; u < 8; u++) idx[u] = __ldg(&csr[j + u]);
        uint4 uv[8];
#pragma unroll
        for (int u = 0; u < 8; u++)
            uv[u] = *reinterpret_cast<const uint4*>(fp + (size_t)idx[u] * FEAT);
#pragma unroll
        for (int u = 0; u < 8; u++) acc_u4(acc, uv[u]);
    }
    for (; j < end; j++) {
        int nb = __ldg(&csr[j]);
        uint4 u = *reinterpret_cast<const uint4*>(fp + (size_t)nb * FEAT);
        acc_u4(acc, u);
    }

    float iv = invd[node];
    __half2 p0 = __floats2half2_rn(acc[0] * iv, acc[1] * iv);
    __half2 p1 = __floats2half2_rn(acc[2] * iv, acc[3] * iv);
    __half2 p2 = __floats2half2_rn(acc[4] * iv, acc[5] * iv);
    __half2 p3 = __floats2half2_rn(acc[6] * iv, acc[7] * iv);
    uint4 o = make_uint4(reinterpret_cast<uint32_t&>(p0), reinterpret_cast<uint32_t&>(p1),
                         reinterpret_cast<uint32_t&>(p2), reinterpret_cast<uint32_t&>(p3));
    *reinterpret_cast<uint4*>(agg16 + (size_t)node * FEAT + lane * 8) = o;
}

// ---------------- shared GEMM core layout ----------------
#define PITCHB 272
#define SM_AH  0
#define SM_AL  34816
#define SM_BH  69632
#define SM_BL  104448
#define SM_TOT_MMA 139264

// Main dual-GEMM accumulation into D. agg fp16; root fp32 (plain cached loads).
#define GEMM_MAIN_LOOP(AGG16, ROOT, WHI, WLO)                                                 \
    for (int phase = 0; phase < 2; phase++) {                                                 \
        const __nv_bfloat16* BsrcH = (WHI) + (size_t)phase * 16384;                           \
        const __nv_bfloat16* BsrcL = (WLO) + (size_t)phase * 16384;                           \
        __syncthreads();                                                                      \
        for (int i = tid; i < 128 * 32; i += 256) {                                           \
            int r = i >> 5, g = i & 31;                                                       \
            float4 v = make_float4(0.f, 0.f, 0.f, 0.f);                                       \
            int row = row0 + r;                                                               \
            if (row < n) {                                                                    \
                if (phase == 0)                                                               \
                    v = load_h4_as_f4((AGG16) + (size_t)row * FEAT + g * 4);                  \
                else                                                                          \
                    v = *reinterpret_cast<const float4*>((ROOT) + (size_t)row * FEAT + g * 4);\
            }                                                                                 \
            uint32_t off = (uint32_t)(r * PITCHB + g * 8);                                    \
            split_store(smem, SM_AH + off, SM_AL + off, v);                                   \
        }                                                                                     \
        for (int i = tid; i < 128 * 32; i += 256) {                                           \
            int j = i >> 5, g = i & 31;                                                       \
            uint2 hi2 = reinterpret_cast<const uint2*>(BsrcH)[i];                             \
            uint2 lo2 = reinterpret_cast<const uint2*>(BsrcL)[i];                             \
            uint32_t off = (uint32_t)(j * PITCHB + g * 8);                                    \
            *reinterpret_cast<uint2*>(smem + SM_BH + off) = hi2;                              \
            *reinterpret_cast<uint2*>(smem + SM_BL + off) = lo2;                              \
        }                                                                                     \
        __syncthreads();                                                                      \
        _Pragma("unroll")                                                                     \
        for (int ks = 0; ks < 8; ks++) {                                                      \
            const uint32_t k0b = (uint32_t)(ks * 32);                                         \
            uint32_t ahi[2][4], alo[2][4];                                                    \
            _Pragma("unroll")                                                                 \
            for (int mt = 0; mt < 2; mt++) {                                                  \
                uint32_t addr = sbase + SM_AH                                                 \
                              + (uint32_t)((wr * 32 + mt * 16 + a_row_part) * PITCHB)         \
                              + k0b + a_koff;                                                 \
                ldsm_x4(ahi[mt], addr);                                                       \
                ldsm_x4(alo[mt], addr + (SM_AL - SM_AH));                                     \
            }                                                                                 \
            uint32_t bhi[8][2], blo[8][2];                                                    \
            _Pragma("unroll")                                                                 \
            for (int nq = 0; nq < 4; nq++) {                                                  \
                uint32_t addr = sbase + SM_BH                                                 \
                              + (uint32_t)((wc * 64 + nq * 16 + b_row_part) * PITCHB)         \
                              + k0b + b_koff;                                                 \
                uint32_t r4[4];                                                               \
                ldsm_x4(r4, addr);                                                            \
                bhi[nq * 2][0] = r4[0]; bhi[nq * 2][1] = r4[1];                               \
                bhi[nq * 2 + 1][0] = r4[2]; bhi[nq * 2 + 1][1] = r4[3];                       \
                ldsm_x4(r4, addr + (SM_BL - SM_BH));                                          \
                blo[nq * 2][0] = r4[0]; blo[nq * 2][1] = r4[1];                               \
                blo[nq * 2 + 1][0] = r4[2]; blo[nq * 2 + 1][1] = r4[3];                       \
            }                                                                                 \
            _Pragma("unroll")                                                                 \
            for (int mt = 0; mt < 2; mt++)                                                    \
                _Pragma("unroll")                                                             \
                for (int nt = 0; nt < 8; nt++) {                                              \
                    mma_bf16(D[mt][nt], ahi[mt], bhi[nt][0], bhi[nt][1]);                     \
                    mma_bf16(D[mt][nt], ahi[mt], blo[nt][0], blo[nt][1]);                     \
                    mma_bf16(D[mt][nt], alo[mt], bhi[nt][0], bhi[nt][1]);                     \
                }                                                                             \
        }                                                                                     \
    }

// ---------------- layers 1-2: dual GEMM, write h fp32 + fp16 ----------------
__global__ __launch_bounds__(256, 1) void sage_gemm_mma(
        const __half* __restrict__ agg16, const float* __restrict__ root,
        const __nv_bfloat16* __restrict__ Whi, const __nv_bfloat16* __restrict__ Wlo,
        const float* __restrict__ b,
        float* __restrict__ out32, __half* __restrict__ out16, int n) {
    extern __shared__ char smem[];
    const uint32_t sbase = smem_u32(smem);
    const int tid  = threadIdx.x;
    const int wid  = tid >> 5;
    const int lane = tid & 31;
    const int wr   = wid & 3;
    const int wc   = wid >> 2;
    const int grp  = lane >> 2;
    const int tig  = lane & 3;
    const int t8   = lane >> 3;
    const int rr   = lane & 7;
    const int row0 = blockIdx.x * 128;

    const int a_row_part = (t8 & 1) * 8 + rr;
    const uint32_t a_koff = (uint32_t)((t8 >> 1) * 16);
    const int b_row_part = (t8 >> 1) * 8 + rr;
    const uint32_t b_koff = (uint32_t)((t8 & 1) * 16);

    float D[2][8][4];
#pragma unroll
    for (int mt = 0; mt < 2; mt++)
#pragma unroll
        for (int nt = 0; nt < 8; nt++)
#pragma unroll
            for (int k = 0; k < 4; k++) D[mt][nt][k] = 0.0f;

    GEMM_MAIN_LOOP(agg16, root, Whi, Wlo)

#pragma unroll
    for (int mt = 0; mt < 2; mt++) {
        int row_lo = row0 + wr * 32 + mt * 16 + grp;
        int row_hi = row_lo + 8;
#pragma unroll
        for (int nt = 0; nt < 8; nt++) {
            int c0 = wc * 64 + nt * 8 + tig * 2;
            float bx = __ldg(b + c0);
            float by = __ldg(b + c0 + 1);
            if (row_lo < n) {
                float2 o;
                o.x = fmaxf(D[mt][nt][0] + bx, 0.0f);
                o.y = fmaxf(D[mt][nt][1] + by, 0.0f);
                *reinterpret_cast<float2*>(out32 + (size_t)row_lo * FEAT + c0) = o;
                __half2 h = __floats2half2_rn(o.x, o.y);
                *reinterpret_cast<uint32_t*>(out16 + (size_t)row_lo * FEAT + c0) =
                    reinterpret_cast<uint32_t&>(h);
            }
            if (row_hi < n) {
                float2 o;
                o.x = fmaxf(D[mt][nt][2] + bx, 0.0f);
                o.y = fmaxf(D[mt][nt][3] + by, 0.0f);
                *reinterpret_cast<float2*>(out32 + (size_t)row_hi * FEAT + c0) = o;
                __half2 h = __floats2half2_rn(o.x, o.y);
                *reinterpret_cast<uint32_t*>(out16 + (size_t)row_hi * FEAT + c0) =
                    reinterpret_cast<uint32_t&>(h);
            }
        }
    }
}

// ---------------- layer 3: dual GEMM + fused 8-channel head projection -> y[N,16] ----------------
__device__ __forceinline__ const float* head_row(int j,
        const float* Wal, const float* Wsl, const float* Wel,
        const float* War, const float* Wsr, const float* Wer) {
    if (j < 3)  return Wal + j * 128;
    if (j < 5)  return Wsl + (j - 3) * 128;
    if (j < 8)  return Wel + (j - 5) * 128;
    if (j < 11) return War + (j - 8) * 128;
    if (j < 13) return Wsr + (j - 11) * 128;
    return Wer + (j - 13) * 128;
}

__global__ __launch_bounds__(256, 1) void sage_gemm_proj(
        const __half* __restrict__ agg16, const float* __restrict__ root,
        const __nv_bfloat16* __restrict__ Whi, const __nv_bfloat16* __restrict__ Wlo,
        const float* __restrict__ b,
        const float* __restrict__ Wal, const float* __restrict__ War, const float* __restrict__ ba,
        const float* __restrict__ Wsl, const float* __restrict__ Wsr, const float* __restrict__ bs,
        const float* __restrict__ Wel, const float* __restrict__ Wer, const float* __restrict__ be,
        float* __restrict__ y, int n) {
    extern __shared__ char smem[];
    __shared__ float sbias[8];
    const uint32_t sbase = smem_u32(smem);
    const int tid  = threadIdx.x;
    const int wid  = tid >> 5;
    const int lane = tid & 31;
    const int wr   = wid & 3;
    const int wc   = wid >> 2;
    const int grp  = lane >> 2;
    const int tig  = lane & 3;
    const int t8   = lane >> 3;
    const int rr   = lane & 7;
    const int row0 = blockIdx.x * 128;

    const int a_row_part = (t8 & 1) * 8 + rr;
    const uint32_t a_koff = (uint32_t)((t8 >> 1) * 16);
    const int b_row_part = (t8 >> 1) * 8 + rr;
    const uint32_t b_koff = (uint32_t)((t8 & 1) * 16);

    float D[2][8][4];
#pragma unroll
    for (int mt = 0; mt < 2; mt++)
#pragma unroll
        for (int nt = 0; nt < 8; nt++)
#pragma unroll
            for (int k = 0; k < 4; k++) D[mt][nt][k] = 0.0f;

    GEMM_MAIN_LOOP(agg16, root, Whi, Wlo)

    __syncthreads();

#pragma unroll
    for (int mt = 0; mt < 2; mt++) {
        int r_lo = wr * 32 + mt * 16 + grp;
        int r_hi = r_lo + 8;
#pragma unroll
        for (int nt = 0; nt < 8; nt++) {
            int c0 = wc * 64 + nt * 8 + tig * 2;
            float bx = __ldg(b + c0);
            float by = __ldg(b + c0 + 1);
            float h0x = fmaxf(D[mt][nt][0] + bx, 0.0f);
            float h0y = fmaxf(D[mt][nt][1] + by, 0.0f);
            float h1x = fmaxf(D[mt][nt][2] + bx, 0.0f);
            float h1y = fmaxf(D[mt][nt][3] + by, 0.0f);
            float h0xh = __bfloat162float(__float2bfloat16_rn(h0x));
            float h0yh = __bfloat162float(__float2bfloat16_rn(h0y));
            float h1xh = __bfloat162float(__float2bfloat16_rn(h1x));
            float h1yh = __bfloat162float(__float2bfloat16_rn(h1y));
            uint32_t off_lo = (uint32_t)(r_lo * PITCHB + c0 * 2);
            uint32_t off_hi = (uint32_t)(r_hi * PITCHB + c0 * 2);
            *reinterpret_cast<uint32_t*>(smem + SM_AH + off_lo) = pack_bf16x2(h0x, h0y);
            *reinterpret_cast<uint32_t*>(smem + SM_AL + off_lo) = pack_bf16x2(h0x - h0xh, h0y - h0yh);
            *reinterpret_cast<uint32_t*>(smem + SM_AH + off_hi) = pack_bf16x2(h1x, h1y);
            *reinterpret_cast<uint32_t*>(smem + SM_AL + off_hi) = pack_bf16x2(h1x - h1xh, h1y - h1yh);
        }
    }
    for (int i = tid; i < 16 * 32; i += 256) {
        int j = i >> 5, g = i & 31;
        const float* src = head_row(j, Wal, Wsl, Wel, War, Wsr, Wer);
        float4 v = reinterpret_cast<const float4*>(src)[g];
        uint32_t off = (uint32_t)(j * PITCHB + g * 8);
        split_store(smem, SM_BH + off, SM_BL + off, v);
    }
    if (tid < 3)  sbias[tid] = ba[tid];
    if (tid >= 8 && tid < 10) sbias[3 + tid - 8] = bs[tid - 8];
    if (tid >= 16 && tid < 19) sbias[5 + tid - 16] = be[tid - 16];
    __syncthreads();

    float D2[2][4];
#pragma unroll
    for (int nt = 0; nt < 2; nt++)
#pragma unroll
        for (int k = 0; k < 4; k++) D2[nt][k] = 0.0f;

#pragma unroll
    for (int ks = 0; ks < 8; ks++) {
        const uint32_t k0b = (uint32_t)(ks * 32);
        uint32_t ahi[4], alo[4];
        uint32_t aaddr = sbase + SM_AH + (uint32_t)((wid * 16 + a_row_part) * PITCHB) + k0b + a_koff;
        ldsm_x4(ahi, aaddr);
        ldsm_x4(alo, aaddr + (SM_AL - SM_AH));

        uint32_t baddr = sbase + SM_BH + (uint32_t)(b_row_part * PITCHB) + k0b + b_koff;
        uint32_t bh4[4], bl4[4];
        ldsm_x4(bh4, baddr);
        ldsm_x4(bl4, baddr + (SM_BL - SM_BH));

#pragma unroll
        for (int nt = 0; nt < 2; nt++) {
            mma_bf16(D2[nt], ahi, bh4[nt * 2], bh4[nt * 2 + 1]);
            mma_bf16(D2[nt], ahi, bl4[nt * 2], bl4[nt * 2 + 1]);
            mma_bf16(D2[nt], alo, bh4[nt * 2], bh4[nt * 2 + 1]);
        }
    }

    {
        int row_lo = row0 + wid * 16 + grp;
        int row_hi = row_lo + 8;
#pragma unroll
        for (int nt = 0; nt < 2; nt++) {
            int c0 = nt * 8 + tig * 2;
            float bx = (nt == 1) ? sbias[tig * 2]     : 0.0f;
            float by = (nt == 1) ? sbias[tig * 2 + 1] : 0.0f;
            if (row_lo < n) {
                float2 o = make_float2(D2[nt][0] + bx, D2[nt][1] + by);
                *reinterpret_cast<float2*>(y + (size_t)row_lo * 16 + c0) = o;
            }
            if (row_hi < n) {
                float2 o = make_float2(D2[nt][2] + bx, D2[nt][3] + by);
                *reinterpret_cast<float2*>(y + (size_t)row_hi * 16 + c0) = o;
            }
        }
    }
}

// ---------------- head gather: 2 lanes per node, unroll 4 ----------------
__global__ __launch_bounds__(256) void head_gather_kernel(
        const float* __restrict__ y,
        const int* __restrict__ csr, const int* __restrict__ off,
        const float* __restrict__ invd, float* __restrict__ out, int n) {
    int gtid = blockIdx.x * blockDim.x + threadIdx.x;
    int node = gtid >> 1;
    int half = gtid & 1;
    if (node >= n) return;

    int beg = off[node];
    int end = off[node + 1];

    const float* yp = y + half * 4;
    float4 s = make_float4(0.f, 0.f, 0.f, 0.f);

    int j = beg;
    for (; j + 3 < end; j += 4) {
        int i0 = __ldg(&csr[j]);
        int i1 = __ldg(&csr[j + 1]);
        int i2 = __ldg(&csr[j + 2]);
        int i3 = __ldg(&csr[j + 3]);
        float4 v0 = *reinterpret_cast<const float4*>(yp + (size_t)i0 * 16);
        float4 v1 = *reinterpret_cast<const float4*>(yp + (size_t)i1 * 16);
        float4 v2 = *reinterpret_cast<const float4*>(yp + (size_t)i2 * 16);
        float4 v3 = *reinterpret_cast<const float4*>(yp + (size_t)i3 * 16);
        s.x += v0.x + v1.x + v2.x + v3.x;
        s.y += v0.y + v1.y + v2.y + v3.y;
        s.z += v0.z + v1.z + v2.z + v3.z;
        s.w += v0.w + v1.w + v2.w + v3.w;
    }
    for (; j < end; j++) {
        int i0 = __ldg(&csr[j]);
        float4 v = *reinterpret_cast<const float4*>(yp + (size_t)i0 * 16);
        s.x += v.x; s.y += v.y; s.z += v.z; s.w += v.w;
    }

    float iv = invd[node];
    float4 r = *reinterpret_cast<const float4*>(y + (size_t)node * 16 + 8 + half * 4);
    float o0 = s.x * iv + r.x;
    float o1 = s.y * iv + r.y;
    float o2 = s.z * iv + r.z;
    float o3 = s.w * iv + r.w;

    if (half == 0) {
        out[(size_t)node * 3 + 0] = o0;
        out[(size_t)node * 3 + 1] = o1;
        out[(size_t)node * 3 + 2] = o2;
        float* sex = out + (size_t)n * 3;
        sex[(size_t)node * 2 + 0] = o3;
    } else {
        float* sex = out + (size_t)n * 3;
        sex[(size_t)node * 2 + 1] = o0;
        float* eth = out + (size_t)n * 5;
        eth[(size_t)node * 3 + 0] = o1;
        eth[(size_t)node * 3 + 1] = o2;
        eth[(size_t)node * 3 + 2] = o3;
    }
}

// ---------------- launch ----------------
extern "C" void kernel_launch(void* const* d_in, const int* in_sizes, int n_in,
                              void* d_out, int out_size) {
    const float* x  = (const float*)d_in[0];
    const int*   ei = (const int*)d_in[1];
    const float *W1l = (const float*)d_in[2],  *W1r = (const float*)d_in[3],  *b1 = (const float*)d_in[4];
    const float *W2l = (const float*)d_in[5],  *W2r = (const float*)d_in[6],  *b2 = (const float*)d_in[7];
    const float *W3l = (const float*)d_in[8],  *W3r = (const float*)d_in[9],  *b3 = (const float*)d_in[10];
    const float *Wal = (const float*)d_in[11], *War = (const float*)d_in[12], *ba = (const float*)d_in[13];
    const float *Wsl = (const float*)d_in[14], *Wsr = (const float*)d_in[15], *bs = (const float*)d_in[16];
    const float *Wel = (const float*)d_in[17], *Wer = (const float*)d_in[18], *be = (const float*)d_in[19];
    float* out = (float*)d_out;

    const int N = in_sizes[0] / FEAT;
    const int E = in_sizes[1] / 2;
    const int* srcIdx = ei;
    const int* dstIdx = ei + E;

    float *h32A, *h32B, *invd, *y;
    __half *agg16, *x16, *h16A, *h16B;
    __nv_bfloat16 *whi, *wlo;
    int *degi, *off, *pos, *bsum, *csr;
    cudaGetSymbolAddress((void**)&agg16, g_agg16);
    cudaGetSymbolAddress((void**)&h32A, g_h32A);
    cudaGetSymbolAddress((void**)&h32B, g_h32B);
    cudaGetSymbolAddress((void**)&x16,  g_x16);
    cudaGetSymbolAddress((void**)&h16A, g_h16A);
    cudaGetSymbolAddress((void**)&h16B, g_h16B);
    cudaGetSymbolAddress((void**)&invd, g_invd);
    cudaGetSymbolAddress((void**)&degi, g_degi);
    cudaGetSymbolAddress((void**)&off,  g_off);
    cudaGetSymbolAddress((void**)&pos,  g_pos);
    cudaGetSymbolAddress((void**)&bsum, g_bsum);
    cudaGetSymbolAddress((void**)&csr,  g_csr);
    cudaGetSymbolAddress((void**)&y,    g_y);
    cudaGetSymbolAddress((void**)&whi,  g_whi);
    cudaGetSymbolAddress((void**)&wlo,  g_wlo);

    cudaFuncSetAttribute(sage_gemm_mma,  cudaFuncAttributeMaxDynamicSharedMemorySize, SM_TOT_MMA);
    cudaFuncSetAttribute(sage_gemm_proj, cudaFuncAttributeMaxDynamicSharedMemorySize, SM_TOT_MMA);

    // ---- prep (cvt16 | wsplit | hist) + CSR build ----
    const int n4 = N * FEAT / 4;
    const int cvtBlocks = (n4 + 255) / 256;
    const int wsBlocks  = (6 * 4096 + 255) / 256;
    const int E4 = E / 4;                      // E = 3.2M divisible by 4
    const int histBlocks = (E4 + 255) / 256;

    cudaMemsetAsync(degi, 0, (size_t)N * sizeof(int));
    prep_kernel<<<cvtBlocks + wsBlocks + histBlocks, 256>>>(
        x, x16, n4, cvtBlocks,
        W1l, W1r, W2l, W2r, W3l, W3r, whi, wlo, wsBlocks,
        dstIdx, degi, E4);

    const int nb = (N + 1023) / 1024;
    scan1_kernel<<<nb, 1024>>>(degi, off, bsum, N);
    scan3_kernel<<<(N + 255) / 256, 256>>>(off, bsum, pos, degi, invd, N, E, nb);
    fill_kernel<<<(E4 + 255) / 256, 256>>>(srcIdx, dstIdx, pos, csr, E4);

    const int gatherBlocks = (int)(((long long)N * 16 + 255) / 256);
    const int gemmBlocks = (N + 127) / 128;

    // layer 1: gather x16; root = x -> h32A + h16A
    gather16_kernel<<<gatherBlocks, 256>>>(x16, agg16, csr, off, invd, N);
    sage_gemm_mma<<<gemmBlocks, 256, SM_TOT_MMA>>>(agg16, x, whi, wlo, b1, h32A, h16A, N);

    // layer 2: gather h16A; root = h32A -> h32B + h16B
    gather16_kernel<<<gatherBlocks, 256>>>(h16A, agg16, csr, off, invd, N);
    sage_gemm_mma<<<gemmBlocks, 256, SM_TOT_MMA>>>(agg16, h32A, whi + 32768, wlo + 32768, b2, h32B, h16B, N);

    // layer 3: gather h16B; root = h32B -> fused projection -> y[N,16]
    gather16_kernel<<<gatherBlocks, 256>>>(h16B, agg16, csr, off, invd, N);
    sage_gemm_proj<<<gemmBlocks, 256, SM_TOT_MMA>>>(agg16, h32B, whi + 65536, wlo + 65536, b3,
                                                    Wal, War, ba, Wsl, Wsr, bs, Wel, Wer, be,
                                                    y, N);

    // heads: 16-dim gather-mean + root (2 lanes per node)
    head_gather_kernel<<<(N * 2 + 255) / 256, 256>>>(y, csr, off, invd, out, N);
}

// round 15
// speedup vs baseline: 1.0033x; 1.0033x over previous
#include <cuda_runtime.h>
#include <cuda_bf16.h>
#include <cuda_fp16.h>
#include <cstdint>

#define NODES 100000
#define EDGES 3200000
#define FEAT  128

// ---------------- scratch (static device memory; no allocation) ----------------
__device__ __half g_agg16[(size_t)NODES * FEAT];
__device__ __half g_x16  [(size_t)NODES * FEAT];
__device__ __half g_hiA  [(size_t)NODES * FEAT];   // h layer output, fp16 hi
__device__ __half g_loA  [(size_t)NODES * FEAT];   // h layer output, fp16 residual
__device__ __half g_hiB  [(size_t)NODES * FEAT];
__device__ __half g_loB  [(size_t)NODES * FEAT];
__device__ float  g_invd[NODES];
__device__ int    g_degi[NODES];
__device__ int    g_off [NODES + 1];
__device__ int    g_pos [NODES];
__device__ int    g_bsum[128];
__device__ int    g_csr [EDGES];
__device__ float  g_y   [(size_t)NODES * 16];      // cols 0-7: l-proj, 8-15: r-proj(+bias)
__device__ __nv_bfloat16 g_whi[6 * 16384];
__device__ __nv_bfloat16 g_wlo[6 * 16384];

// ================= helpers =================
__device__ __forceinline__ uint32_t smem_u32(const void* p) {
    uint32_t a;
    asm("{ .reg .u64 t; cvta.to.shared.u64 t, %1; cvt.u32.u64 %0, t; }" : "=r"(a) : "l"(p));
    return a;
}

__device__ __forceinline__ uint32_t pack_bf16x2(float a, float b) {
    __nv_bfloat162 h = __floats2bfloat162_rn(a, b);
    return reinterpret_cast<uint32_t&>(h);
}

__device__ __forceinline__ void ldsm_x4(uint32_t (&r)[4], uint32_t addr) {
    asm volatile("ldmatrix.sync.aligned.m8n8.x4.shared.b16 {%0,%1,%2,%3}, [%4];"
                 : "=r"(r[0]), "=r"(r[1]), "=r"(r[2]), "=r"(r[3]) : "r"(addr));
}

__device__ __forceinline__ void mma_bf16(float (&d)[4], const uint32_t (&a)[4],
                                         uint32_t b0, uint32_t b1) {
    asm volatile("mma.sync.aligned.m16n8k16.row.col.f32.bf16.bf16.f32 "
                 "{%0,%1,%2,%3}, {%4,%5,%6,%7}, {%8,%9}, {%0,%1,%2,%3};"
                 : "+f"(d[0]), "+f"(d[1]), "+f"(d[2]), "+f"(d[3])
                 : "r"(a[0]), "r"(a[1]), "r"(a[2]), "r"(a[3]), "r"(b0), "r"(b1));
}

__device__ __forceinline__ void acc_u4(float (&acc)[8], uint4 u) {
    float2 f0 = __half22float2(reinterpret_cast<__half2&>(u.x));
    float2 f1 = __half22float2(reinterpret_cast<__half2&>(u.y));
    float2 f2 = __half22float2(reinterpret_cast<__half2&>(u.z));
    float2 f3 = __half22float2(reinterpret_cast<__half2&>(u.w));
    acc[0] += f0.x; acc[1] += f0.y; acc[2] += f1.x; acc[3] += f1.y;
    acc[4] += f2.x; acc[5] += f2.y; acc[6] += f3.x; acc[7] += f3.y;
}

__device__ __forceinline__ float4 load_h4_as_f4(const __half* p) {
    uint2 u = *reinterpret_cast<const uint2*>(p);
    float2 a = __half22float2(reinterpret_cast<__half2&>(u.x));
    float2 b = __half22float2(reinterpret_cast<__half2&>(u.y));
    return make_float4(a.x, a.y, b.x, b.y);
}

__device__ __forceinline__ void split_store(char* smem, uint32_t offHi, uint32_t offLo, float4 v) {
    float hx = __bfloat162float(__float2bfloat16_rn(v.x));
    float hy = __bfloat162float(__float2bfloat16_rn(v.y));
    float hz = __bfloat162float(__float2bfloat16_rn(v.z));
    float hw = __bfloat162float(__float2bfloat16_rn(v.w));
    uint2 hi2 = make_uint2(pack_bf16x2(v.x, v.y), pack_bf16x2(v.z, v.w));
    uint2 lo2 = make_uint2(pack_bf16x2(v.x - hx, v.y - hy), pack_bf16x2(v.z - hz, v.w - hw));
    *reinterpret_cast<uint2*>(smem + offHi) = hi2;
    *reinterpret_cast<uint2*>(smem + offLo) = lo2;
}

// ---------------- merged prep: cvt16 | wsplit | hist, role by block range ----------------
__global__ __launch_bounds__(256) void prep_kernel(
        const float* __restrict__ x, __half* __restrict__ x16, int n4, int cvtBlocks,
        const float* __restrict__ w0, const float* __restrict__ w1,
        const float* __restrict__ w2, const float* __restrict__ w3,
        const float* __restrict__ w4, const float* __restrict__ w5,
        __nv_bfloat16* __restrict__ whi, __nv_bfloat16* __restrict__ wlo, int wsBlocks,
        const int* __restrict__ dst, int* __restrict__ degi, int E2) {
    int blk = blockIdx.x;
    int tid = threadIdx.x;

    if (blk < cvtBlocks) {
        int i = blk * 256 + tid;
        if (i < n4) {
            float4 v = reinterpret_cast<const float4*>(x)[i];
            __half2 h0 = __floats2half2_rn(v.x, v.y);
            __half2 h1 = __floats2half2_rn(v.z, v.w);
            uint2 o = make_uint2(reinterpret_cast<uint32_t&>(h0), reinterpret_cast<uint32_t&>(h1));
            reinterpret_cast<uint2*>(x16)[i] = o;
        }
        return;
    }
    blk -= cvtBlocks;

    if (blk < wsBlocks) {
        int i = blk * 256 + tid;
        if (i < 6 * 4096) {
            const float* src;
            switch (i >> 12) {
                case 0: src = w0; break; case 1: src = w1; break; case 2: src = w2; break;
                case 3: src = w3; break; case 4: src = w4; break; default: src = w5; break;
            }
            float4 v = reinterpret_cast<const float4*>(src)[i & 4095];
            float hx = __bfloat162float(__float2bfloat16_rn(v.x));
            float hy = __bfloat162float(__float2bfloat16_rn(v.y));
            float hz = __bfloat162float(__float2bfloat16_rn(v.z));
            float hw = __bfloat162float(__float2bfloat16_rn(v.w));
            uint2 hi2 = make_uint2(pack_bf16x2(v.x, v.y), pack_bf16x2(v.z, v.w));
            uint2 lo2 = make_uint2(pack_bf16x2(v.x - hx, v.y - hy), pack_bf16x2(v.z - hz, v.w - hw));
            reinterpret_cast<uint2*>(whi)[i] = hi2;
            reinterpret_cast<uint2*>(wlo)[i] = lo2;
        }
        return;
    }
    blk -= wsBlocks;

    int e = blk * 256 + tid;
    if (e < E2) {
        int2 d = reinterpret_cast<const int2*>(dst)[e];
        atomicAdd(&degi[d.x], 1);
        atomicAdd(&degi[d.y], 1);
    }
}

// ---------------- CSR scans ----------------
__global__ void scan1_kernel(const int* __restrict__ degi, int* __restrict__ off,
                             int* __restrict__ bsum, int n) {
    __shared__ int s[1024];
    int t = threadIdx.x;
    int i = blockIdx.x * 1024 + t;
    int v = (i < n) ? degi[i] : 0;
    s[t] = v;
    __syncthreads();
#pragma unroll
    for (int d = 1; d < 1024; d <<= 1) {
        int x = (t >= d) ? s[t - d] : 0;
        __syncthreads();
        s[t] += x;
        __syncthreads();
    }
    if (i < n) off[i] = s[t] - v;
    if (t == 1023) bsum[blockIdx.x] = s[t];
}

// scan3 with inline bsum scan (scan2 merged)
__global__ void scan3_kernel(int* __restrict__ off, const int* __restrict__ bsum,
                             int* __restrict__ pos, const int* __restrict__ degi,
                             float* __restrict__ invd, int n, int E, int nb) {
    __shared__ int s[128];
    int t = threadIdx.x;
    int v = 0;
    if (t < 128) {
        v = (t < nb) ? bsum[t] : 0;
        s[t] = v;
    }
    __syncthreads();
#pragma unroll
    for (int d = 1; d < 128; d <<= 1) {
        int x = 0;
        if (t < 128 && t >= d) x = s[t - d];
        __syncthreads();
        if (t < 128) s[t] += x;
        __syncthreads();
    }
    if (t < 128) s[t] -= v;   // exclusive
    __syncthreads();

    int i = blockIdx.x * blockDim.x + t;
    if (i < n) {
        int o = off[i] + s[i >> 10];
        off[i] = o;
        pos[i] = o;
        invd[i] = 1.0f / fmaxf((float)degi[i], 1.0f);
    }
    if (i == 0) off[n] = E;
}

// vectorized fill: 2 edges per thread
__global__ void fill_kernel(const int* __restrict__ src, const int* __restrict__ dst,
                            int* __restrict__ pos, int* __restrict__ csr, int E2) {
    int e = blockIdx.x * blockDim.x + threadIdx.x;
    if (e < E2) {
        int2 s = reinterpret_cast<const int2*>(src)[e];
        int2 d = reinterpret_cast<const int2*>(dst)[e];
        int p0 = atomicAdd(&pos[d.x], 1);
        csr[p0] = s.x;
        int p1 = atomicAdd(&pos[d.y], 1);
        csr[p1] = s.y;
    }
}

// ---------------- gather-mean: half-warp per node, fp16 in -> fp16 agg out, unroll 8 ----------------
__global__ __launch_bounds__(256) void gather16_kernel(
        const __half* __restrict__ feat, __half* __restrict__ agg16,
        const int* __restrict__ csr, const int* __restrict__ off,
        const float* __restrict__ invd, int n) {
    int gtid = blockIdx.x * blockDim.x + threadIdx.x;
    int node = gtid >> 4;
    int lane = gtid & 15;
    if (node >= n) return;

    int beg = off[node];
    int end = off[node + 1];

    float acc[8];
#pragma unroll
    for (int k = 0; k < 8; k++) acc[k] = 0.0f;

    const __half* fp = feat + lane * 8;

    int j = beg;
    for (; j + 7 < end; j += 8) {
        int idx[8];
#pragma unroll
        for (int u = 0; u < 8; u++) idx[u] = __ldg(&csr[j + u]);
        uint4 uv[8];
#pragma unroll
        for (int u = 0; u < 8; u++)
            uv[u] = *reinterpret_cast<const uint4*>(fp + (size_t)idx[u] * FEAT);
#pragma unroll
        for (int u = 0; u < 8; u++) acc_u4(acc, uv[u]);
    }
    for (; j < end; j++) {
        int nb = __ldg(&csr[j]);
        uint4 u = *reinterpret_cast<const uint4*>(fp + (size_t)nb * FEAT);
        acc_u4(acc, u);
    }

    float iv = invd[node];
    __half2 p0 = __floats2half2_rn(acc[0] * iv, acc[1] * iv);
    __half2 p1 = __floats2half2_rn(acc[2] * iv, acc[3] * iv);
    __half2 p2 = __floats2half2_rn(acc[4] * iv, acc[5] * iv);
    __half2 p3 = __floats2half2_rn(acc[6] * iv, acc[7] * iv);
    uint4 o = make_uint4(reinterpret_cast<uint32_t&>(p0), reinterpret_cast<uint32_t&>(p1),
                         reinterpret_cast<uint32_t&>(p2), reinterpret_cast<uint32_t&>(p3));
    *reinterpret_cast<uint4*>(agg16 + (size_t)node * FEAT + lane * 8) = o;
}

// ---------------- shared GEMM core layout ----------------
#define PITCHB 272
#define SM_AH  0
#define SM_AL  34816
#define SM_BH  69632
#define SM_BL  104448
#define SM_TOT_MMA 139264

// Main dual-GEMM accumulation into D. agg fp16 hi; root either fp32 (ROOT32 != 0)
// or fp16 hi+lo pair (reconstructed).
#define GEMM_MAIN_LOOP(AGG16, ROOT32, ROOTHI, ROOTLO, WHI, WLO)                               \
    for (int phase = 0; phase < 2; phase++) {                                                 \
        const __nv_bfloat16* BsrcH = (WHI) + (size_t)phase * 16384;                           \
        const __nv_bfloat16* BsrcL = (WLO) + (size_t)phase * 16384;                           \
        __syncthreads();                                                                      \
        for (int i = tid; i < 128 * 32; i += 256) {                                           \
            int r = i >> 5, g = i & 31;                                                       \
            float4 v = make_float4(0.f, 0.f, 0.f, 0.f);                                       \
            int row = row0 + r;                                                               \
            if (row < n) {                                                                    \
                if (phase == 0) {                                                             \
                    v = load_h4_as_f4((AGG16) + (size_t)row * FEAT + g * 4);                  \
                } else if (ROOT32) {                                                          \
                    v = *reinterpret_cast<const float4*>((ROOT32) + (size_t)row * FEAT + g * 4); \
                } else {                                                                      \
                    float4 vh = load_h4_as_f4((ROOTHI) + (size_t)row * FEAT + g * 4);         \
                    float4 vl = load_h4_as_f4((ROOTLO) + (size_t)row * FEAT + g * 4);         \
                    v = make_float4(vh.x + vl.x, vh.y + vl.y, vh.z + vl.z, vh.w + vl.w);      \
                }                                                                             \
            }                                                                                 \
            uint32_t off = (uint32_t)(r * PITCHB + g * 8);                                    \
            split_store(smem, SM_AH + off, SM_AL + off, v);                                   \
        }                                                                                     \
        for (int i = tid; i < 128 * 32; i += 256) {                                           \
            int j = i >> 5, g = i & 31;                                                       \
            uint2 hi2 = reinterpret_cast<const uint2*>(BsrcH)[i];                             \
            uint2 lo2 = reinterpret_cast<const uint2*>(BsrcL)[i];                             \
            uint32_t off = (uint32_t)(j * PITCHB + g * 8);                                    \
            *reinterpret_cast<uint2*>(smem + SM_BH + off) = hi2;                              \
            *reinterpret_cast<uint2*>(smem + SM_BL + off) = lo2;                              \
        }                                                                                     \
        __syncthreads();                                                                      \
        _Pragma("unroll")                                                                     \
        for (int ks = 0; ks < 8; ks++) {                                                      \
            const uint32_t k0b = (uint32_t)(ks * 32);                                         \
            uint32_t ahi[2][4], alo[2][4];                                                    \
            _Pragma("unroll")                                                                 \
            for (int mt = 0; mt < 2; mt++) {                                                  \
                uint32_t addr = sbase + SM_AH                                                 \
                              + (uint32_t)((wr * 32 + mt * 16 + a_row_part) * PITCHB)         \
                              + k0b + a_koff;                                                 \
                ldsm_x4(ahi[mt], addr);                                                       \
                ldsm_x4(alo[mt], addr + (SM_AL - SM_AH));                                     \
            }                                                                                 \
            uint32_t bhi[8][2], blo[8][2];                                                    \
            _Pragma("unroll")                                                                 \
            for (int nq = 0; nq < 4; nq++) {                                                  \
                uint32_t addr = sbase + SM_BH                                                 \
                              + (uint32_t)((wc * 64 + nq * 16 + b_row_part) * PITCHB)         \
                              + k0b + b_koff;                                                 \
                uint32_t r4[4];                                                               \
                ldsm_x4(r4, addr);                                                            \
                bhi[nq * 2][0] = r4[0]; bhi[nq * 2][1] = r4[1];                               \
                bhi[nq * 2 + 1][0] = r4[2]; bhi[nq * 2 + 1][1] = r4[3];                       \
                ldsm_x4(r4, addr + (SM_BL - SM_BH));                                          \
                blo[nq * 2][0] = r4[0]; blo[nq * 2][1] = r4[1];                               \
                blo[nq * 2 + 1][0] = r4[2]; blo[nq * 2 + 1][1] = r4[3];                       \
            }                                                                                 \
            _Pragma("unroll")                                                                 \
            for (int mt = 0; mt < 2; mt++)                                                    \
                _Pragma("unroll")                                                             \
                for (int nt = 0; nt < 8; nt++) {                                              \
                    mma_bf16(D[mt][nt], ahi[mt], bhi[nt][0], bhi[nt][1]);                     \
                    mma_bf16(D[mt][nt], ahi[mt], blo[nt][0], blo[nt][1]);                     \
                    mma_bf16(D[mt][nt], alo[mt], bhi[nt][0], bhi[nt][1]);                     \
                }                                                                             \
        }                                                                                     \
    }

// ---------------- layers 1-2: dual GEMM, write h as fp16 hi + fp16 residual ----------------
__global__ __launch_bounds__(256, 1) void sage_gemm_mma(
        const __half* __restrict__ agg16,
        const float* __restrict__ root32,
        const __half* __restrict__ rootHi, const __half* __restrict__ rootLo,
        const __nv_bfloat16* __restrict__ Whi, const __nv_bfloat16* __restrict__ Wlo,
        const float* __restrict__ b,
        __half* __restrict__ outHi, __half* __restrict__ outLo, int n) {
    extern __shared__ char smem[];
    const uint32_t sbase = smem_u32(smem);
    const int tid  = threadIdx.x;
    const int wid  = tid >> 5;
    const int lane = tid & 31;
    const int wr   = wid & 3;
    const int wc   = wid >> 2;
    const int grp  = lane >> 2;
    const int tig  = lane & 3;
    const int t8   = lane >> 3;
    const int rr   = lane & 7;
    const int row0 = blockIdx.x * 128;

    const int a_row_part = (t8 & 1) * 8 + rr;
    const uint32_t a_koff = (uint32_t)((t8 >> 1) * 16);
    const int b_row_part = (t8 >> 1) * 8 + rr;
    const uint32_t b_koff = (uint32_t)((t8 & 1) * 16);

    float D[2][8][4];
#pragma unroll
    for (int mt = 0; mt < 2; mt++)
#pragma unroll
        for (int nt = 0; nt < 8; nt++)
#pragma unroll
            for (int k = 0; k < 4; k++) D[mt][nt][k] = 0.0f;

    GEMM_MAIN_LOOP(agg16, root32, rootHi, rootLo, Whi, Wlo)

#pragma unroll
    for (int mt = 0; mt < 2; mt++) {
        int row_lo = row0 + wr * 32 + mt * 16 + grp;
        int row_hi = row_lo + 8;
#pragma unroll
        for (int nt = 0; nt < 8; nt++) {
            int c0 = wc * 64 + nt * 8 + tig * 2;
            float bx = __ldg(b + c0);
            float by = __ldg(b + c0 + 1);
            if (row_lo < n) {
                float ox = fmaxf(D[mt][nt][0] + bx, 0.0f);
                float oy = fmaxf(D[mt][nt][1] + by, 0.0f);
                __half2 hi = __floats2half2_rn(ox, oy);
                float hx = __half2float(__low2half(hi));
                float hy = __half2float(__high2half(hi));
                __half2 lo = __floats2half2_rn(ox - hx, oy - hy);
                *reinterpret_cast<uint32_t*>(outHi + (size_t)row_lo * FEAT + c0) =
                    reinterpret_cast<uint32_t&>(hi);
                *reinterpret_cast<uint32_t*>(outLo + (size_t)row_lo * FEAT + c0) =
                    reinterpret_cast<uint32_t&>(lo);
            }
            if (row_hi < n) {
                float ox = fmaxf(D[mt][nt][2] + bx, 0.0f);
                float oy = fmaxf(D[mt][nt][3] + by, 0.0f);
                __half2 hi = __floats2half2_rn(ox, oy);
                float hx = __half2float(__low2half(hi));
                float hy = __half2float(__high2half(hi));
                __half2 lo = __floats2half2_rn(ox - hx, oy - hy);
                *reinterpret_cast<uint32_t*>(outHi + (size_t)row_hi * FEAT + c0) =
                    reinterpret_cast<uint32_t&>(hi);
                *reinterpret_cast<uint32_t*>(outLo + (size_t)row_hi * FEAT + c0) =
                    reinterpret_cast<uint32_t&>(lo);
            }
        }
    }
}

// ---------------- layer 3: dual GEMM + fused 8-channel head projection -> y[N,16] ----------------
__device__ __forceinline__ const float* head_row(int j,
        const float* Wal, const float* Wsl, const float* Wel,
        const float* War, const float* Wsr, const float* Wer) {
    if (j < 3)  return Wal + j * 128;
    if (j < 5)  return Wsl + (j - 3) * 128;
    if (j < 8)  return Wel + (j - 5) * 128;
    if (j < 11) return War + (j - 8) * 128;
    if (j < 13) return Wsr + (j - 11) * 128;
    return Wer + (j - 13) * 128;
}

__global__ __launch_bounds__(256, 1) void sage_gemm_proj(
        const __half* __restrict__ agg16,
        const float* __restrict__ root32,
        const __half* __restrict__ rootHi, const __half* __restrict__ rootLo,
        const __nv_bfloat16* __restrict__ Whi, const __nv_bfloat16* __restrict__ Wlo,
        const float* __restrict__ b,
        const float* __restrict__ Wal, const float* __restrict__ War, const float* __restrict__ ba,
        const float* __restrict__ Wsl, const float* __restrict__ Wsr, const float* __restrict__ bs,
        const float* __restrict__ Wel, const float* __restrict__ Wer, const float* __restrict__ be,
        float* __restrict__ y, int n) {
    extern __shared__ char smem[];
    __shared__ float sbias[8];
    const uint32_t sbase = smem_u32(smem);
    const int tid  = threadIdx.x;
    const int wid  = tid >> 5;
    const int lane = tid & 31;
    const int wr   = wid & 3;
    const int wc   = wid >> 2;
    const int grp  = lane >> 2;
    const int tig  = lane & 3;
    const int t8   = lane >> 3;
    const int rr   = lane & 7;
    const int row0 = blockIdx.x * 128;

    const int a_row_part = (t8 & 1) * 8 + rr;
    const uint32_t a_koff = (uint32_t)((t8 >> 1) * 16);
    const int b_row_part = (t8 >> 1) * 8 + rr;
    const uint32_t b_koff = (uint32_t)((t8 & 1) * 16);

    float D[2][8][4];
#pragma unroll
    for (int mt = 0; mt < 2; mt++)
#pragma unroll
        for (int nt = 0; nt < 8; nt++)
#pragma unroll
            for (int k = 0; k < 4; k++) D[mt][nt][k] = 0.0f;

    GEMM_MAIN_LOOP(agg16, root32, rootHi, rootLo, Whi, Wlo)

    __syncthreads();

#pragma unroll
    for (int mt = 0; mt < 2; mt++) {
        int r_lo = wr * 32 + mt * 16 + grp;
        int r_hi = r_lo + 8;
#pragma unroll
        for (int nt = 0; nt < 8; nt++) {
            int c0 = wc * 64 + nt * 8 + tig * 2;
            float bx = __ldg(b + c0);
            float by = __ldg(b + c0 + 1);
            float h0x = fmaxf(D[mt][nt][0] + bx, 0.0f);
            float h0y = fmaxf(D[mt][nt][1] + by, 0.0f);
            float h1x = fmaxf(D[mt][nt][2] + bx, 0.0f);
            float h1y = fmaxf(D[mt][nt][3] + by, 0.0f);
            float h0xh = __bfloat162float(__float2bfloat16_rn(h0x));
            float h0yh = __bfloat162float(__float2bfloat16_rn(h0y));
            float h1xh = __bfloat162float(__float2bfloat16_rn(h1x));
            float h1yh = __bfloat162float(__float2bfloat16_rn(h1y));
            uint32_t off_lo = (uint32_t)(r_lo * PITCHB + c0 * 2);
            uint32_t off_hi = (uint32_t)(r_hi * PITCHB + c0 * 2);
            *reinterpret_cast<uint32_t*>(smem + SM_AH + off_lo) = pack_bf16x2(h0x, h0y);
            *reinterpret_cast<uint32_t*>(smem + SM_AL + off_lo) = pack_bf16x2(h0x - h0xh, h0y - h0yh);
            *reinterpret_cast<uint32_t*>(smem + SM_AH + off_hi) = pack_bf16x2(h1x, h1y);
            *reinterpret_cast<uint32_t*>(smem + SM_AL + off_hi) = pack_bf16x2(h1x - h1xh, h1y - h1yh);
        }
    }
    for (int i = tid; i < 16 * 32; i += 256) {
        int j = i >> 5, g = i & 31;
        const float* src = head_row(j, Wal, Wsl, Wel, War, Wsr, Wer);
        float4 v = reinterpret_cast<const float4*>(src)[g];
        uint32_t off = (uint32_t)(j * PITCHB + g * 8);
        split_store(smem, SM_BH + off, SM_BL + off, v);
    }
    if (tid < 3)  sbias[tid] = ba[tid];
    if (tid >= 8 && tid < 10) sbias[3 + tid - 8] = bs[tid - 8];
    if (tid >= 16 && tid < 19) sbias[5 + tid - 16] = be[tid - 16];
    __syncthreads();

    float D2[2][4];
#pragma unroll
    for (int nt = 0; nt < 2; nt++)
#pragma unroll
        for (int k = 0; k < 4; k++) D2[nt][k] = 0.0f;

#pragma unroll
    for (int ks = 0; ks < 8; ks++) {
        const uint32_t k0b = (uint32_t)(ks * 32);
        uint32_t ahi[4], alo[4];
        uint32_t aaddr = sbase + SM_AH + (uint32_t)((wid * 16 + a_row_part) * PITCHB) + k0b + a_koff;
        ldsm_x4(ahi, aaddr);
        ldsm_x4(alo, aaddr + (SM_AL - SM_AH));

        uint32_t baddr = sbase + SM_BH + (uint32_t)(b_row_part * PITCHB) + k0b + b_koff;
        uint32_t bh4[4], bl4[4];
        ldsm_x4(bh4, baddr);
        ldsm_x4(bl4, baddr + (SM_BL - SM_BH));

#pragma unroll
        for (int nt = 0; nt < 2; nt++) {
            mma_bf16(D2[nt], ahi, bh4[nt * 2], bh4[nt * 2 + 1]);
            mma_bf16(D2[nt], ahi, bl4[nt * 2], bl4[nt * 2 + 1]);
            mma_bf16(D2[nt], alo, bh4[nt * 2], bh4[nt * 2 + 1]);
        }
    }

    {
        int row_lo = row0 + wid * 16 + grp;
        int row_hi = row_lo + 8;
#pragma unroll
        for (int nt = 0; nt < 2; nt++) {
            int c0 = nt * 8 + tig * 2;
            float bx = (nt == 1) ? sbias[tig * 2]     : 0.0f;
            float by = (nt == 1) ? sbias[tig * 2 + 1] : 0.0f;
            if (row_lo < n) {
                float2 o = make_float2(D2[nt][0] + bx, D2[nt][1] + by);
                *reinterpret_cast<float2*>(y + (size_t)row_lo * 16 + c0) = o;
            }
            if (row_hi < n) {
                float2 o = make_float2(D2[nt][2] + bx, D2[nt][3] + by);
                *reinterpret_cast<float2*>(y + (size_t)row_hi * 16 + c0) = o;
            }
        }
    }
}

// ---------------- head gather: 2 lanes per node, unroll 4 ----------------
__global__ __launch_bounds__(256) void head_gather_kernel(
        const float* __restrict__ y,
        const int* __restrict__ csr, const int* __restrict__ off,
        const float* __restrict__ invd, float* __restrict__ out, int n) {
    int gtid = blockIdx.x * blockDim.x + threadIdx.x;
    int node = gtid >> 1;
    int half = gtid & 1;
    if (node >= n) return;

    int beg = off[node];
    int end = off[node + 1];

    const float* yp = y + half * 4;
    float4 s = make_float4(0.f, 0.f, 0.f, 0.f);

    int j = beg;
    for (; j + 3 < end; j += 4) {
        int i0 = __ldg(&csr[j]);
        int i1 = __ldg(&csr[j + 1]);
        int i2 = __ldg(&csr[j + 2]);
        int i3 = __ldg(&csr[j + 3]);
        float4 v0 = *reinterpret_cast<const float4*>(yp + (size_t)i0 * 16);
        float4 v1 = *reinterpret_cast<const float4*>(yp + (size_t)i1 * 16);
        float4 v2 = *reinterpret_cast<const float4*>(yp + (size_t)i2 * 16);
        float4 v3 = *reinterpret_cast<const float4*>(yp + (size_t)i3 * 16);
        s.x += v0.x + v1.x + v2.x + v3.x;
        s.y += v0.y + v1.y + v2.y + v3.y;
        s.z += v0.z + v1.z + v2.z + v3.z;
        s.w += v0.w + v1.w + v2.w + v3.w;
    }
    for (; j < end; j++) {
        int i0 = __ldg(&csr[j]);
        float4 v = *reinterpret_cast<const float4*>(yp + (size_t)i0 * 16);
        s.x += v.x; s.y += v.y; s.z += v.z; s.w += v.w;
    }

    float iv = invd[node];
    float4 r = *reinterpret_cast<const float4*>(y + (size_t)node * 16 + 8 + half * 4);
    float o0 = s.x * iv + r.x;
    float o1 = s.y * iv + r.y;
    float o2 = s.z * iv + r.z;
    float o3 = s.w * iv + r.w;

    if (half == 0) {
        out[(size_t)node * 3 + 0] = o0;
        out[(size_t)node * 3 + 1] = o1;
        out[(size_t)node * 3 + 2] = o2;
        float* sex = out + (size_t)n * 3;
        sex[(size_t)node * 2 + 0] = o3;
    } else {
        float* sex = out + (size_t)n * 3;
        sex[(size_t)node * 2 + 1] = o0;
        float* eth = out + (size_t)n * 5;
        eth[(size_t)node * 3 + 0] = o1;
        eth[(size_t)node * 3 + 1] = o2;
        eth[(size_t)node * 3 + 2] = o3;
    }
}

// ---------------- launch ----------------
extern "C" void kernel_launch(void* const* d_in, const int* in_sizes, int n_in,
                              void* d_out, int out_size) {
    const float* x  = (const float*)d_in[0];
    const int*   ei = (const int*)d_in[1];
    const float *W1l = (const float*)d_in[2],  *W1r = (const float*)d_in[3],  *b1 = (const float*)d_in[4];
    const float *W2l = (const float*)d_in[5],  *W2r = (const float*)d_in[6],  *b2 = (const float*)d_in[7];
    const float *W3l = (const float*)d_in[8],  *W3r = (const float*)d_in[9],  *b3 = (const float*)d_in[10];
    const float *Wal = (const float*)d_in[11], *War = (const float*)d_in[12], *ba = (const float*)d_in[13];
    const float *Wsl = (const float*)d_in[14], *Wsr = (const float*)d_in[15], *bs = (const float*)d_in[16];
    const float *Wel = (const float*)d_in[17], *Wer = (const float*)d_in[18], *be = (const float*)d_in[19];
    float* out = (float*)d_out;

    const int N = in_sizes[0] / FEAT;
    const int E = in_sizes[1] / 2;
    const int* srcIdx = ei;
    const int* dstIdx = ei + E;

    float *invd, *y;
    __half *agg16, *x16, *hiA, *loA, *hiB, *loB;
    __nv_bfloat16 *whi, *wlo;
    int *degi, *off, *pos, *bsum, *csr;
    cudaGetSymbolAddress((void**)&agg16, g_agg16);
    cudaGetSymbolAddress((void**)&x16,  g_x16);
    cudaGetSymbolAddress((void**)&hiA,  g_hiA);
    cudaGetSymbolAddress((void**)&loA,  g_loA);
    cudaGetSymbolAddress((void**)&hiB,  g_hiB);
    cudaGetSymbolAddress((void**)&loB,  g_loB);
    cudaGetSymbolAddress((void**)&invd, g_invd);
    cudaGetSymbolAddress((void**)&degi, g_degi);
    cudaGetSymbolAddress((void**)&off,  g_off);
    cudaGetSymbolAddress((void**)&pos,  g_pos);
    cudaGetSymbolAddress((void**)&bsum, g_bsum);
    cudaGetSymbolAddress((void**)&csr,  g_csr);
    cudaGetSymbolAddress((void**)&y,    g_y);
    cudaGetSymbolAddress((void**)&whi,  g_whi);
    cudaGetSymbolAddress((void**)&wlo,  g_wlo);

    cudaFuncSetAttribute(sage_gemm_mma,  cudaFuncAttributeMaxDynamicSharedMemorySize, SM_TOT_MMA);
    cudaFuncSetAttribute(sage_gemm_proj, cudaFuncAttributeMaxDynamicSharedMemorySize, SM_TOT_MMA);

    // ---- prep (cvt16 | wsplit | hist) + CSR build ----
    const int n4 = N * FEAT / 4;
    const int cvtBlocks = (n4 + 255) / 256;
    const int wsBlocks  = (6 * 4096 + 255) / 256;
    const int E2 = E / 2;
    const int histBlocks = (E2 + 255) / 256;

    cudaMemsetAsync(degi, 0, (size_t)N * sizeof(int));
    prep_kernel<<<cvtBlocks + wsBlocks + histBlocks, 256>>>(
        x, x16, n4, cvtBlocks,
        W1l, W1r, W2l, W2r, W3l, W3r, whi, wlo, wsBlocks,
        dstIdx, degi, E2);

    const int nb = (N + 1023) / 1024;
    scan1_kernel<<<nb, 1024>>>(degi, off, bsum, N);
    scan3_kernel<<<(N + 255) / 256, 256>>>(off, bsum, pos, degi, invd, N, E, nb);
    fill_kernel<<<(E2 + 255) / 256, 256>>>(srcIdx, dstIdx, pos, csr, E2);

    const int gatherBlocks = (int)(((long long)N * 16 + 255) / 256);
    const int gemmBlocks = (N + 127) / 128;

    // layer 1: gather x16; root = x (fp32) -> hiA + loA
    gather16_kernel<<<gatherBlocks, 256>>>(x16, agg16, csr, off, invd, N);
    sage_gemm_mma<<<gemmBlocks, 256, SM_TOT_MMA>>>(agg16, x, (const __half*)0, (const __half*)0,
                                                   whi, wlo, b1, hiA, loA, N);

    // layer 2: gather hiA; root = hiA+loA -> hiB + loB
    gather16_kernel<<<gatherBlocks, 256>>>(hiA, agg16, csr, off, invd, N);
    sage_gemm_mma<<<gemmBlocks, 256, SM_TOT_MMA>>>(agg16, (const float*)0, hiA, loA,
                                                   whi + 32768, wlo + 32768, b2, hiB, loB, N);

    // layer 3: gather hiB; root = hiB+loB -> fused projection -> y[N,16]
    gather16_kernel<<<gatherBlocks, 256>>>(hiB, agg16, csr, off, invd, N);
    sage_gemm_proj<<<gemmBlocks, 256, SM_TOT_MMA>>>(agg16, (const float*)0, hiB, loB,
                                                    whi + 65536, wlo + 65536, b3,
                                                    Wal, War, ba, Wsl, Wsr, bs, Wel, Wer, be,
                                                    y, N);

    // heads: 16-dim gather-mean + root (2 lanes per node)
    head_gather_kernel<<<(N * 2 + 255) / 256, 256>>>(y, csr, off, invd, out, N);
}

// round 16
// speedup vs baseline: 1.0266x; 1.0232x over previous
#include <cuda_runtime.h>
#include <cuda_bf16.h>
#include <cuda_fp16.h>
#include <cstdint>

#define NODES 100000
#define EDGES 3200000
#define FEAT  128

// ---------------- scratch (static device memory; no allocation) ----------------
__device__ __half g_agg16[(size_t)NODES * FEAT];
__device__ __half g_x16  [(size_t)NODES * FEAT];
__device__ __half g_hiA  [(size_t)NODES * FEAT];   // h layer output, fp16 hi
__device__ __half g_loA  [(size_t)NODES * FEAT];   // h layer output, fp16 residual
__device__ __half g_hiB  [(size_t)NODES * FEAT];
__device__ __half g_loB  [(size_t)NODES * FEAT];
__device__ float  g_invd[NODES];
__device__ int    g_degi[NODES];
__device__ int    g_off [NODES + 1];
__device__ int    g_pos [NODES];
__device__ int    g_bsum[128];
__device__ int    g_csr [EDGES];
__device__ float  g_y   [(size_t)NODES * 16];      // cols 0-7: l-proj, 8-15: r-proj(+bias)
__device__ __nv_bfloat16 g_whi[6 * 16384];
__device__ __nv_bfloat16 g_wlo[6 * 16384];

// ================= helpers =================
__device__ __forceinline__ uint32_t smem_u32(const void* p) {
    uint32_t a;
    asm("{ .reg .u64 t; cvta.to.shared.u64 t, %1; cvt.u32.u64 %0, t; }" : "=r"(a) : "l"(p));
    return a;
}

__device__ __forceinline__ uint32_t pack_bf16x2(float a, float b) {
    __nv_bfloat162 h = __floats2bfloat162_rn(a, b);
    return reinterpret_cast<uint32_t&>(h);
}

__device__ __forceinline__ void ldsm_x4(uint32_t (&r)[4], uint32_t addr) {
    asm volatile("ldmatrix.sync.aligned.m8n8.x4.shared.b16 {%0,%1,%2,%3}, [%4];"
                 : "=r"(r[0]), "=r"(r[1]), "=r"(r[2]), "=r"(r[3]) : "r"(addr));
}

__device__ __forceinline__ void mma_bf16(float (&d)[4], const uint32_t (&a)[4],
                                         uint32_t b0, uint32_t b1) {
    asm volatile("mma.sync.aligned.m16n8k16.row.col.f32.bf16.bf16.f32 "
                 "{%0,%1,%2,%3}, {%4,%5,%6,%7}, {%8,%9}, {%0,%1,%2,%3};"
                 : "+f"(d[0]), "+f"(d[1]), "+f"(d[2]), "+f"(d[3])
                 : "r"(a[0]), "r"(a[1]), "r"(a[2]), "r"(a[3]), "r"(b0), "r"(b1));
}

__device__ __forceinline__ void acc_u4(float (&acc)[8], uint4 u) {
    float2 f0 = __half22float2(reinterpret_cast<__half2&>(u.x));
    float2 f1 = __half22float2(reinterpret_cast<__half2&>(u.y));
    float2 f2 = __half22float2(reinterpret_cast<__half2&>(u.z));
    float2 f3 = __half22float2(reinterpret_cast<__half2&>(u.w));
    acc[0] += f0.x; acc[1] += f0.y; acc[2] += f1.x; acc[3] += f1.y;
    acc[4] += f2.x; acc[5] += f2.y; acc[6] += f3.x; acc[7] += f3.y;
}

// pairwise fp16 add of two feature vectors (one rounding per element pair)
__device__ __forceinline__ uint4 hadd2_u4(uint4 a, uint4 b) {
    __half2 r0 = __hadd2(reinterpret_cast<__half2&>(a.x), reinterpret_cast<__half2&>(b.x));
    __half2 r1 = __hadd2(reinterpret_cast<__half2&>(a.y), reinterpret_cast<__half2&>(b.y));
    __half2 r2 = __hadd2(reinterpret_cast<__half2&>(a.z), reinterpret_cast<__half2&>(b.z));
    __half2 r3 = __hadd2(reinterpret_cast<__half2&>(a.w), reinterpret_cast<__half2&>(b.w));
    return make_uint4(reinterpret_cast<uint32_t&>(r0), reinterpret_cast<uint32_t&>(r1),
                      reinterpret_cast<uint32_t&>(r2), reinterpret_cast<uint32_t&>(r3));
}

__device__ __forceinline__ float4 load_h4_as_f4(const __half* p) {
    uint2 u = *reinterpret_cast<const uint2*>(p);
    float2 a = __half22float2(reinterpret_cast<__half2&>(u.x));
    float2 b = __half22float2(reinterpret_cast<__half2&>(u.y));
    return make_float4(a.x, a.y, b.x, b.y);
}

__device__ __forceinline__ void split_store(char* smem, uint32_t offHi, uint32_t offLo, float4 v) {
    float hx = __bfloat162float(__float2bfloat16_rn(v.x));
    float hy = __bfloat162float(__float2bfloat16_rn(v.y));
    float hz = __bfloat162float(__float2bfloat16_rn(v.z));
    float hw = __bfloat162float(__float2bfloat16_rn(v.w));
    uint2 hi2 = make_uint2(pack_bf16x2(v.x, v.y), pack_bf16x2(v.z, v.w));
    uint2 lo2 = make_uint2(pack_bf16x2(v.x - hx, v.y - hy), pack_bf16x2(v.z - hz, v.w - hw));
    *reinterpret_cast<uint2*>(smem + offHi) = hi2;
    *reinterpret_cast<uint2*>(smem + offLo) = lo2;
}

// ---------------- merged prep: cvt16 | wsplit | hist, role by block range ----------------
__global__ __launch_bounds__(256) void prep_kernel(
        const float* __restrict__ x, __half* __restrict__ x16, int n4, int cvtBlocks,
        const float* __restrict__ w0, const float* __restrict__ w1,
        const float* __restrict__ w2, const float* __restrict__ w3,
        const float* __restrict__ w4, const float* __restrict__ w5,
        __nv_bfloat16* __restrict__ whi, __nv_bfloat16* __restrict__ wlo, int wsBlocks,
        const int* __restrict__ dst, int* __restrict__ degi, int E2) {
    int blk = blockIdx.x;
    int tid = threadIdx.x;

    if (blk < cvtBlocks) {
        int i = blk * 256 + tid;
        if (i < n4) {
            float4 v = reinterpret_cast<const float4*>(x)[i];
            __half2 h0 = __floats2half2_rn(v.x, v.y);
            __half2 h1 = __floats2half2_rn(v.z, v.w);
            uint2 o = make_uint2(reinterpret_cast<uint32_t&>(h0), reinterpret_cast<uint32_t&>(h1));
            reinterpret_cast<uint2*>(x16)[i] = o;
        }
        return;
    }
    blk -= cvtBlocks;

    if (blk < wsBlocks) {
        int i = blk * 256 + tid;
        if (i < 6 * 4096) {
            const float* src;
            switch (i >> 12) {
                case 0: src = w0; break; case 1: src = w1; break; case 2: src = w2; break;
                case 3: src = w3; break; case 4: src = w4; break; default: src = w5; break;
            }
            float4 v = reinterpret_cast<const float4*>(src)[i & 4095];
            float hx = __bfloat162float(__float2bfloat16_rn(v.x));
            float hy = __bfloat162float(__float2bfloat16_rn(v.y));
            float hz = __bfloat162float(__float2bfloat16_rn(v.z));
            float hw = __bfloat162float(__float2bfloat16_rn(v.w));
            uint2 hi2 = make_uint2(pack_bf16x2(v.x, v.y), pack_bf16x2(v.z, v.w));
            uint2 lo2 = make_uint2(pack_bf16x2(v.x - hx, v.y - hy), pack_bf16x2(v.z - hz, v.w - hw));
            reinterpret_cast<uint2*>(whi)[i] = hi2;
            reinterpret_cast<uint2*>(wlo)[i] = lo2;
        }
        return;
    }
    blk -= wsBlocks;

    int e = blk * 256 + tid;
    if (e < E2) {
        int2 d = reinterpret_cast<const int2*>(dst)[e];
        atomicAdd(&degi[d.x], 1);
        atomicAdd(&degi[d.y], 1);
    }
}

// ---------------- CSR scans ----------------
__global__ void scan1_kernel(const int* __restrict__ degi, int* __restrict__ off,
                             int* __restrict__ bsum, int n) {
    __shared__ int s[1024];
    int t = threadIdx.x;
    int i = blockIdx.x * 1024 + t;
    int v = (i < n) ? degi[i] : 0;
    s[t] = v;
    __syncthreads();
#pragma unroll
    for (int d = 1; d < 1024; d <<= 1) {
        int x = (t >= d) ? s[t - d] : 0;
        __syncthreads();
        s[t] += x;
        __syncthreads();
    }
    if (i < n) off[i] = s[t] - v;
    if (t == 1023) bsum[blockIdx.x] = s[t];
}

// scan3 with inline bsum scan (scan2 merged)
__global__ void scan3_kernel(int* __restrict__ off, const int* __restrict__ bsum,
                             int* __restrict__ pos, const int* __restrict__ degi,
                             float* __restrict__ invd, int n, int E, int nb) {
    __shared__ int s[128];
    int t = threadIdx.x;
    int v = 0;
    if (t < 128) {
        v = (t < nb) ? bsum[t] : 0;
        s[t] = v;
    }
    __syncthreads();
#pragma unroll
    for (int d = 1; d < 128; d <<= 1) {
        int x = 0;
        if (t < 128 && t >= d) x = s[t - d];
        __syncthreads();
        if (t < 128) s[t] += x;
        __syncthreads();
    }
    if (t < 128) s[t] -= v;   // exclusive
    __syncthreads();

    int i = blockIdx.x * blockDim.x + t;
    if (i < n) {
        int o = off[i] + s[i >> 10];
        off[i] = o;
        pos[i] = o;
        invd[i] = 1.0f / fmaxf((float)degi[i], 1.0f);
    }
    if (i == 0) off[n] = E;
}

// vectorized fill: 2 edges per thread
__global__ void fill_kernel(const int* __restrict__ src, const int* __restrict__ dst,
                            int* __restrict__ pos, int* __restrict__ csr, int E2) {
    int e = blockIdx.x * blockDim.x + threadIdx.x;
    if (e < E2) {
        int2 s = reinterpret_cast<const int2*>(src)[e];
        int2 d = reinterpret_cast<const int2*>(dst)[e];
        int p0 = atomicAdd(&pos[d.x], 1);
        csr[p0] = s.x;
        int p1 = atomicAdd(&pos[d.y], 1);
        csr[p1] = s.y;
    }
}

// ---------------- gather-mean: half-warp per node, fp16 in, pairwise HADD2, unroll 8 ----------------
__global__ __launch_bounds__(256) void gather16_kernel(
        const __half* __restrict__ feat, __half* __restrict__ agg16,
        const int* __restrict__ csr, const int* __restrict__ off,
        const float* __restrict__ invd, int n) {
    int gtid = blockIdx.x * blockDim.x + threadIdx.x;
    int node = gtid >> 4;
    int lane = gtid & 15;
    if (node >= n) return;

    int beg = off[node];
    int end = off[node + 1];

    float acc[8];
#pragma unroll
    for (int k = 0; k < 8; k++) acc[k] = 0.0f;

    const __half* fp = feat + lane * 8;

    int j = beg;
    for (; j + 7 < end; j += 8) {
        int idx[8];
#pragma unroll
        for (int u = 0; u < 8; u++) idx[u] = __ldg(&csr[j + u]);
        uint4 uv[8];
#pragma unroll
        for (int u = 0; u < 8; u++)
            uv[u] = *reinterpret_cast<const uint4*>(fp + (size_t)idx[u] * FEAT);
        // pairwise fp16 pre-reduction: 8 vectors -> 4, then fp32 accumulate
#pragma unroll
        for (int p = 0; p < 4; p++) {
            uint4 pv = hadd2_u4(uv[2 * p], uv[2 * p + 1]);
            acc_u4(acc, pv);
        }
    }
    for (; j < end; j++) {
        int nb = __ldg(&csr[j]);
        uint4 u = *reinterpret_cast<const uint4*>(fp + (size_t)nb * FEAT);
        acc_u4(acc, u);
    }

    float iv = invd[node];
    __half2 p0 = __floats2half2_rn(acc[0] * iv, acc[1] * iv);
    __half2 p1 = __floats2half2_rn(acc[2] * iv, acc[3] * iv);
    __half2 p2 = __floats2half2_rn(acc[4] * iv, acc[5] * iv);
    __half2 p3 = __floats2half2_rn(acc[6] * iv, acc[7] * iv);
    uint4 o = make_uint4(reinterpret_cast<uint32_t&>(p0), reinterpret_cast<uint32_t&>(p1),
                         reinterpret_cast<uint32_t&>(p2), reinterpret_cast<uint32_t&>(p3));
    *reinterpret_cast<uint4*>(agg16 + (size_t)node * FEAT + lane * 8) = o;
}

// ---------------- shared GEMM core layout ----------------
#define PITCHB 272
#define SM_AH  0
#define SM_AL  34816
#define SM_BH  69632
#define SM_BL  104448
#define SM_TOT_MMA 139264

// Main dual-GEMM accumulation into D. agg fp16 hi; root either fp32 (ROOT32 != 0)
// or fp16 hi+lo pair (reconstructed).
#define GEMM_MAIN_LOOP(AGG16, ROOT32, ROOTHI, ROOTLO, WHI, WLO)                               \
    for (int phase = 0; phase < 2; phase++) {                                                 \
        const __nv_bfloat16* BsrcH = (WHI) + (size_t)phase * 16384;                           \
        const __nv_bfloat16* BsrcL = (WLO) + (size_t)phase * 16384;                           \
        __syncthreads();                                                                      \
        for (int i = tid; i < 128 * 32; i += 256) {                                           \
            int r = i >> 5, g = i & 31;                                                       \
            float4 v = make_float4(0.f, 0.f, 0.f, 0.f);                                       \
            int row = row0 + r;                                                               \
            if (row < n) {                                                                    \
                if (phase == 0) {                                                             \
                    v = load_h4_as_f4((AGG16) + (size_t)row * FEAT + g * 4);                  \
                } else if (ROOT32) {                                                          \
                    v = *reinterpret_cast<const float4*>((ROOT32) + (size_t)row * FEAT + g * 4); \
                } else {                                                                      \
                    float4 vh = load_h4_as_f4((ROOTHI) + (size_t)row * FEAT + g * 4);         \
                    float4 vl = load_h4_as_f4((ROOTLO) + (size_t)row * FEAT + g * 4);         \
                    v = make_float4(vh.x + vl.x, vh.y + vl.y, vh.z + vl.z, vh.w + vl.w);      \
                }                                                                             \
            }                                                                                 \
            uint32_t off = (uint32_t)(r * PITCHB + g * 8);                                    \
            split_store(smem, SM_AH + off, SM_AL + off, v);                                   \
        }                                                                                     \
        for (int i = tid; i < 128 * 32; i += 256) {                                           \
            int j = i >> 5, g = i & 31;                                                       \
            uint2 hi2 = reinterpret_cast<const uint2*>(BsrcH)[i];                             \
            uint2 lo2 = reinterpret_cast<const uint2*>(BsrcL)[i];                             \
            uint32_t off = (uint32_t)(j * PITCHB + g * 8);                                    \
            *reinterpret_cast<uint2*>(smem + SM_BH + off) = hi2;                              \
            *reinterpret_cast<uint2*>(smem + SM_BL + off) = lo2;                              \
        }                                                                                     \
        __syncthreads();                                                                      \
        _Pragma("unroll")                                                                     \
        for (int ks = 0; ks < 8; ks++) {                                                      \
            const uint32_t k0b = (uint32_t)(ks * 32);                                         \
            uint32_t ahi[2][4], alo[2][4];                                                    \
            _Pragma("unroll")                                                                 \
            for (int mt = 0; mt < 2; mt++) {                                                  \
                uint32_t addr = sbase + SM_AH                                                 \
                              + (uint32_t)((wr * 32 + mt * 16 + a_row_part) * PITCHB)         \
                              + k0b + a_koff;                                                 \
                ldsm_x4(ahi[mt], addr);                                                       \
                ldsm_x4(alo[mt], addr + (SM_AL - SM_AH));                                     \
            }                                                                                 \
            uint32_t bhi[8][2], blo[8][2];                                                    \
            _Pragma("unroll")                                                                 \
            for (int nq = 0; nq < 4; nq++) {                                                  \
                uint32_t addr = sbase + SM_BH                                                 \
                              + (uint32_t)((wc * 64 + nq * 16 + b_row_part) * PITCHB)         \
                              + k0b + b_koff;                                                 \
                uint32_t r4[4];                                                               \
                ldsm_x4(r4, addr);                                                            \
                bhi[nq * 2][0] = r4[0]; bhi[nq * 2][1] = r4[1];                               \
                bhi[nq * 2 + 1][0] = r4[2]; bhi[nq * 2 + 1][1] = r4[3];                       \
                ldsm_x4(r4, addr + (SM_BL - SM_BH));                                          \
                blo[nq * 2][0] = r4[0]; blo[nq * 2][1] = r4[1];                               \
                blo[nq * 2 + 1][0] = r4[2]; blo[nq * 2 + 1][1] = r4[3];                       \
            }                                                                                 \
            _Pragma("unroll")                                                                 \
            for (int mt = 0; mt < 2; mt++)                                                    \
                _Pragma("unroll")                                                             \
                for (int nt = 0; nt < 8; nt++) {                                              \
                    mma_bf16(D[mt][nt], ahi[mt], bhi[nt][0], bhi[nt][1]);                     \
                    mma_bf16(D[mt][nt], ahi[mt], blo[nt][0], blo[nt][1]);                     \
                    mma_bf16(D[mt][nt], alo[mt], bhi[nt][0], bhi[nt][1]);                     \
                }                                                                             \
        }                                                                                     \
    }

// ---------------- layers 1-2: dual GEMM, write h as fp16 hi + fp16 residual ----------------
__global__ __launch_bounds__(256, 1) void sage_gemm_mma(
        const __half* __restrict__ agg16,
        const float* __restrict__ root32,
        const __half* __restrict__ rootHi, const __half* __restrict__ rootLo,
        const __nv_bfloat16* __restrict__ Whi, const __nv_bfloat16* __restrict__ Wlo,
        const float* __restrict__ b,
        __half* __restrict__ outHi, __half* __restrict__ outLo, int n) {
    extern __shared__ char smem[];
    const uint32_t sbase = smem_u32(smem);
    const int tid  = threadIdx.x;
    const int wid  = tid >> 5;
    const int lane = tid & 31;
    const int wr   = wid & 3;
    const int wc   = wid >> 2;
    const int grp  = lane >> 2;
    const int tig  = lane & 3;
    const int t8   = lane >> 3;
    const int rr   = lane & 7;
    const int row0 = blockIdx.x * 128;

    const int a_row_part = (t8 & 1) * 8 + rr;
    const uint32_t a_koff = (uint32_t)((t8 >> 1) * 16);
    const int b_row_part = (t8 >> 1) * 8 + rr;
    const uint32_t b_koff = (uint32_t)((t8 & 1) * 16);

    float D[2][8][4];
#pragma unroll
    for (int mt = 0; mt < 2; mt++)
#pragma unroll
        for (int nt = 0; nt < 8; nt++)
#pragma unroll
            for (int k = 0; k < 4; k++) D[mt][nt][k] = 0.0f;

    GEMM_MAIN_LOOP(agg16, root32, rootHi, rootLo, Whi, Wlo)

#pragma unroll
    for (int mt = 0; mt < 2; mt++) {
        int row_lo = row0 + wr * 32 + mt * 16 + grp;
        int row_hi = row_lo + 8;
#pragma unroll
        for (int nt = 0; nt < 8; nt++) {
            int c0 = wc * 64 + nt * 8 + tig * 2;
            float bx = __ldg(b + c0);
            float by = __ldg(b + c0 + 1);
            if (row_lo < n) {
                float ox = fmaxf(D[mt][nt][0] + bx, 0.0f);
                float oy = fmaxf(D[mt][nt][1] + by, 0.0f);
                __half2 hi = __floats2half2_rn(ox, oy);
                float hx = __half2float(__low2half(hi));
                float hy = __half2float(__high2half(hi));
                __half2 lo = __floats2half2_rn(ox - hx, oy - hy);
                *reinterpret_cast<uint32_t*>(outHi + (size_t)row_lo * FEAT + c0) =
                    reinterpret_cast<uint32_t&>(hi);
                *reinterpret_cast<uint32_t*>(outLo + (size_t)row_lo * FEAT + c0) =
                    reinterpret_cast<uint32_t&>(lo);
            }
            if (row_hi < n) {
                float ox = fmaxf(D[mt][nt][2] + bx, 0.0f);
                float oy = fmaxf(D[mt][nt][3] + by, 0.0f);
                __half2 hi = __floats2half2_rn(ox, oy);
                float hx = __half2float(__low2half(hi));
                float hy = __half2float(__high2half(hi));
                __half2 lo = __floats2half2_rn(ox - hx, oy - hy);
                *reinterpret_cast<uint32_t*>(outHi + (size_t)row_hi * FEAT + c0) =
                    reinterpret_cast<uint32_t&>(hi);
                *reinterpret_cast<uint32_t*>(outLo + (size_t)row_hi * FEAT + c0) =
                    reinterpret_cast<uint32_t&>(lo);
            }
        }
    }
}

// ---------------- layer 3: dual GEMM + fused 8-channel head projection -> y[N,16] ----------------
__device__ __forceinline__ const float* head_row(int j,
        const float* Wal, const float* Wsl, const float* Wel,
        const float* War, const float* Wsr, const float* Wer) {
    if (j < 3)  return Wal + j * 128;
    if (j < 5)  return Wsl + (j - 3) * 128;
    if (j < 8)  return Wel + (j - 5) * 128;
    if (j < 11) return War + (j - 8) * 128;
    if (j < 13) return Wsr + (j - 11) * 128;
    return Wer + (j - 13) * 128;
}

__global__ __launch_bounds__(256, 1) void sage_gemm_proj(
        const __half* __restrict__ agg16,
        const float* __restrict__ root32,
        const __half* __restrict__ rootHi, const __half* __restrict__ rootLo,
        const __nv_bfloat16* __restrict__ Whi, const __nv_bfloat16* __restrict__ Wlo,
        const float* __restrict__ b,
        const float* __restrict__ Wal, const float* __restrict__ War, const float* __restrict__ ba,
        const float* __restrict__ Wsl, const float* __restrict__ Wsr, const float* __restrict__ bs,
        const float* __restrict__ Wel, const float* __restrict__ Wer, const float* __restrict__ be,
        float* __restrict__ y, int n) {
    extern __shared__ char smem[];
    __shared__ float sbias[8];
    const uint32_t sbase = smem_u32(smem);
    const int tid  = threadIdx.x;
    const int wid  = tid >> 5;
    const int lane = tid & 31;
    const int wr   = wid & 3;
    const int wc   = wid >> 2;
    const int grp  = lane >> 2;
    const int tig  = lane & 3;
    const int t8   = lane >> 3;
    const int rr   = lane & 7;
    const int row0 = blockIdx.x * 128;

    const int a_row_part = (t8 & 1) * 8 + rr;
    const uint32_t a_koff = (uint32_t)((t8 >> 1) * 16);
    const int b_row_part = (t8 >> 1) * 8 + rr;
    const uint32_t b_koff = (uint32_t)((t8 & 1) * 16);

    float D[2][8][4];
#pragma unroll
    for (int mt = 0; mt < 2; mt++)
#pragma unroll
        for (int nt = 0; nt < 8; nt++)
#pragma unroll
            for (int k = 0; k < 4; k++) D[mt][nt][k] = 0.0f;

    GEMM_MAIN_LOOP(agg16, root32, rootHi, rootLo, Whi, Wlo)

    __syncthreads();

#pragma unroll
    for (int mt = 0; mt < 2; mt++) {
        int r_lo = wr * 32 + mt * 16 + grp;
        int r_hi = r_lo + 8;
#pragma unroll
        for (int nt = 0; nt < 8; nt++) {
            int c0 = wc * 64 + nt * 8 + tig * 2;
            float bx = __ldg(b + c0);
            float by = __ldg(b + c0 + 1);
            float h0x = fmaxf(D[mt][nt][0] + bx, 0.0f);
            float h0y = fmaxf(D[mt][nt][1] + by, 0.0f);
            float h1x = fmaxf(D[mt][nt][2] + bx, 0.0f);
            float h1y = fmaxf(D[mt][nt][3] + by, 0.0f);
            float h0xh = __bfloat162float(__float2bfloat16_rn(h0x));
            float h0yh = __bfloat162float(__float2bfloat16_rn(h0y));
            float h1xh = __bfloat162float(__float2bfloat16_rn(h1x));
            float h1yh = __bfloat162float(__float2bfloat16_rn(h1y));
            uint32_t off_lo = (uint32_t)(r_lo * PITCHB + c0 * 2);
            uint32_t off_hi = (uint32_t)(r_hi * PITCHB + c0 * 2);
            *reinterpret_cast<uint32_t*>(smem + SM_AH + off_lo) = pack_bf16x2(h0x, h0y);
            *reinterpret_cast<uint32_t*>(smem + SM_AL + off_lo) = pack_bf16x2(h0x - h0xh, h0y - h0yh);
            *reinterpret_cast<uint32_t*>(smem + SM_AH + off_hi) = pack_bf16x2(h1x, h1y);
            *reinterpret_cast<uint32_t*>(smem + SM_AL + off_hi) = pack_bf16x2(h1x - h1xh, h1y - h1yh);
        }
    }
    for (int i = tid; i < 16 * 32; i += 256) {
        int j = i >> 5, g = i & 31;
        const float* src = head_row(j, Wal, Wsl, Wel, War, Wsr, Wer);
        float4 v = reinterpret_cast<const float4*>(src)[g];
        uint32_t off = (uint32_t)(j * PITCHB + g * 8);
        split_store(smem, SM_BH + off, SM_BL + off, v);
    }
    if (tid < 3)  sbias[tid] = ba[tid];
    if (tid >= 8 && tid < 10) sbias[3 + tid - 8] = bs[tid - 8];
    if (tid >= 16 && tid < 19) sbias[5 + tid - 16] = be[tid - 16];
    __syncthreads();

    float D2[2][4];
#pragma unroll
    for (int nt = 0; nt < 2; nt++)
#pragma unroll
        for (int k = 0; k < 4; k++) D2[nt][k] = 0.0f;

#pragma unroll
    for (int ks = 0; ks < 8; ks++) {
        const uint32_t k0b = (uint32_t)(ks * 32);
        uint32_t ahi[4], alo[4];
        uint32_t aaddr = sbase + SM_AH + (uint32_t)((wid * 16 + a_row_part) * PITCHB) + k0b + a_koff;
        ldsm_x4(ahi, aaddr);
        ldsm_x4(alo, aaddr + (SM_AL - SM_AH));

        uint32_t baddr = sbase + SM_BH + (uint32_t)(b_row_part * PITCHB) + k0b + b_koff;
        uint32_t bh4[4], bl4[4];
        ldsm_x4(bh4, baddr);
        ldsm_x4(bl4, baddr + (SM_BL - SM_BH));

#pragma unroll
        for (int nt = 0; nt < 2; nt++) {
            mma_bf16(D2[nt], ahi, bh4[nt * 2], bh4[nt * 2 + 1]);
            mma_bf16(D2[nt], ahi, bl4[nt * 2], bl4[nt * 2 + 1]);
            mma_bf16(D2[nt], alo, bh4[nt * 2], bh4[nt * 2 + 1]);
        }
    }

    {
        int row_lo = row0 + wid * 16 + grp;
        int row_hi = row_lo + 8;
#pragma unroll
        for (int nt = 0; nt < 2; nt++) {
            int c0 = nt * 8 + tig * 2;
            float bx = (nt == 1) ? sbias[tig * 2]     : 0.0f;
            float by = (nt == 1) ? sbias[tig * 2 + 1] : 0.0f;
            if (row_lo < n) {
                float2 o = make_float2(D2[nt][0] + bx, D2[nt][1] + by);
                *reinterpret_cast<float2*>(y + (size_t)row_lo * 16 + c0) = o;
            }
            if (row_hi < n) {
                float2 o = make_float2(D2[nt][2] + bx, D2[nt][3] + by);
                *reinterpret_cast<float2*>(y + (size_t)row_hi * 16 + c0) = o;
            }
        }
    }
}

// ---------------- head gather: 2 lanes per node, unroll 4 ----------------
__global__ __launch_bounds__(256) void head_gather_kernel(
        const float* __restrict__ y,
        const int* __restrict__ csr, const int* __restrict__ off,
        const float* __restrict__ invd, float* __restrict__ out, int n) {
    int gtid = blockIdx.x * blockDim.x + threadIdx.x;
    int node = gtid >> 1;
    int half = gtid & 1;
    if (node >= n) return;

    int beg = off[node];
    int end = off[node + 1];

    const float* yp = y + half * 4;
    float4 s = make_float4(0.f, 0.f, 0.f, 0.f);

    int j = beg;
    for (; j + 3 < end; j += 4) {
        int i0 = __ldg(&csr[j]);
        int i1 = __ldg(&csr[j + 1]);
        int i2 = __ldg(&csr[j + 2]);
        int i3 = __ldg(&csr[j + 3]);
        float4 v0 = *reinterpret_cast<const float4*>(yp + (size_t)i0 * 16);
        float4 v1 = *reinterpret_cast<const float4*>(yp + (size_t)i1 * 16);
        float4 v2 = *reinterpret_cast<const float4*>(yp + (size_t)i2 * 16);
        float4 v3 = *reinterpret_cast<const float4*>(yp + (size_t)i3 * 16);
        s.x += v0.x + v1.x + v2.x + v3.x;
        s.y += v0.y + v1.y + v2.y + v3.y;
        s.z += v0.z + v1.z + v2.z + v3.z;
        s.w += v0.w + v1.w + v2.w + v3.w;
    }
    for (; j < end; j++) {
        int i0 = __ldg(&csr[j]);
        float4 v = *reinterpret_cast<const float4*>(yp + (size_t)i0 * 16);
        s.x += v.x; s.y += v.y; s.z += v.z; s.w += v.w;
    }

    float iv = invd[node];
    float4 r = *reinterpret_cast<const float4*>(y + (size_t)node * 16 + 8 + half * 4);
    float o0 = s.x * iv + r.x;
    float o1 = s.y * iv + r.y;
    float o2 = s.z * iv + r.z;
    float o3 = s.w * iv + r.w;

    if (half == 0) {
        out[(size_t)node * 3 + 0] = o0;
        out[(size_t)node * 3 + 1] = o1;
        out[(size_t)node * 3 + 2] = o2;
        float* sex = out + (size_t)n * 3;
        sex[(size_t)node * 2 + 0] = o3;
    } else {
        float* sex = out + (size_t)n * 3;
        sex[(size_t)node * 2 + 1] = o0;
        float* eth = out + (size_t)n * 5;
        eth[(size_t)node * 3 + 0] = o1;
        eth[(size_t)node * 3 + 1] = o2;
        eth[(size_t)node * 3 + 2] = o3;
    }
}

// ---------------- launch ----------------
extern "C" void kernel_launch(void* const* d_in, const int* in_sizes, int n_in,
                              void* d_out, int out_size) {
    const float* x  = (const float*)d_in[0];
    const int*   ei = (const int*)d_in[1];
    const float *W1l = (const float*)d_in[2],  *W1r = (const float*)d_in[3],  *b1 = (const float*)d_in[4];
    const float *W2l = (const float*)d_in[5],  *W2r = (const float*)d_in[6],  *b2 = (const float*)d_in[7];
    const float *W3l = (const float*)d_in[8],  *W3r = (const float*)d_in[9],  *b3 = (const float*)d_in[10];
    const float *Wal = (const float*)d_in[11], *War = (const float*)d_in[12], *ba = (const float*)d_in[13];
    const float *Wsl = (const float*)d_in[14], *Wsr = (const float*)d_in[15], *bs = (const float*)d_in[16];
    const float *Wel = (const float*)d_in[17], *Wer = (const float*)d_in[18], *be = (const float*)d_in[19];
    float* out = (float*)d_out;

    const int N = in_sizes[0] / FEAT;
    const int E = in_sizes[1] / 2;
    const int* srcIdx = ei;
    const int* dstIdx = ei + E;

    float *invd, *y;
    __half *agg16, *x16, *hiA, *loA, *hiB, *loB;
    __nv_bfloat16 *whi, *wlo;
    int *degi, *off, *pos, *bsum, *csr;
    cudaGetSymbolAddress((void**)&agg16, g_agg16);
    cudaGetSymbolAddress((void**)&x16,  g_x16);
    cudaGetSymbolAddress((void**)&hiA,  g_hiA);
    cudaGetSymbolAddress((void**)&loA,  g_loA);
    cudaGetSymbolAddress((void**)&hiB,  g_hiB);
    cudaGetSymbolAddress((void**)&loB,  g_loB);
    cudaGetSymbolAddress((void**)&invd, g_invd);
    cudaGetSymbolAddress((void**)&degi, g_degi);
    cudaGetSymbolAddress((void**)&off,  g_off);
    cudaGetSymbolAddress((void**)&pos,  g_pos);
    cudaGetSymbolAddress((void**)&bsum, g_bsum);
    cudaGetSymbolAddress((void**)&csr,  g_csr);
    cudaGetSymbolAddress((void**)&y,    g_y);
    cudaGetSymbolAddress((void**)&whi,  g_whi);
    cudaGetSymbolAddress((void**)&wlo,  g_wlo);

    cudaFuncSetAttribute(sage_gemm_mma,  cudaFuncAttributeMaxDynamicSharedMemorySize, SM_TOT_MMA);
    cudaFuncSetAttribute(sage_gemm_proj, cudaFuncAttributeMaxDynamicSharedMemorySize, SM_TOT_MMA);

    // ---- prep (cvt16 | wsplit | hist) + CSR build ----
    const int n4 = N * FEAT / 4;
    const int cvtBlocks = (n4 + 255) / 256;
    const int wsBlocks  = (6 * 4096 + 255) / 256;
    const int E2 = E / 2;
    const int histBlocks = (E2 + 255) / 256;

    cudaMemsetAsync(degi, 0, (size_t)N * sizeof(int));
    prep_kernel<<<cvtBlocks + wsBlocks + histBlocks, 256>>>(
        x, x16, n4, cvtBlocks,
        W1l, W1r, W2l, W2r, W3l, W3r, whi, wlo, wsBlocks,
        dstIdx, degi, E2);

    const int nb = (N + 1023) / 1024;
    scan1_kernel<<<nb, 1024>>>(degi, off, bsum, N);
    scan3_kernel<<<(N + 255) / 256, 256>>>(off, bsum, pos, degi, invd, N, E, nb);
    fill_kernel<<<(E2 + 255) / 256, 256>>>(srcIdx, dstIdx, pos, csr, E2);

    const int gatherBlocks = (int)(((long long)N * 16 + 255) / 256);
    const int gemmBlocks = (N + 127) / 128;

    // layer 1: gather x16; root = x (fp32) -> hiA + loA
    gather16_kernel<<<gatherBlocks, 256>>>(x16, agg16, csr, off, invd, N);
    sage_gemm_mma<<<gemmBlocks, 256, SM_TOT_MMA>>>(agg16, x, (const __half*)0, (const __half*)0,
                                                   whi, wlo, b1, hiA, loA, N);

    // layer 2: gather hiA; root = hiA+loA -> hiB + loB
    gather16_kernel<<<gatherBlocks, 256>>>(hiA, agg16, csr, off, invd, N);
    sage_gemm_mma<<<gemmBlocks, 256, SM_TOT_MMA>>>(agg16, (const float*)0, hiA, loA,
                                                   whi + 32768, wlo + 32768, b2, hiB, loB, N);

    // layer 3: gather hiB; root = hiB+loB -> fused projection -> y[N,16]
    gather16_kernel<<<gatherBlocks, 256>>>(hiB, agg16, csr, off, invd, N);
    sage_gemm_proj<<<gemmBlocks, 256, SM_TOT_MMA>>>(agg16, (const float*)0, hiB, loB,
                                                    whi + 65536, wlo + 65536, b3,
                                                    Wal, War, ba, Wsl, Wsr, bs, Wel, Wer, be,
                                                    y, N);

    // heads: 16-dim gather-mean + root (2 lanes per node)
    head_gather_kernel<<<(N * 2 + 255) / 256, 256>>>(y, csr, off, invd, out, N);
}